// round 8
// baseline (speedup 1.0000x reference)
#include <cuda_runtime.h>
#include <cuda_bf16.h>
#include <math.h>
#include <stdint.h>

// ---------------------------------------------------------------------------
// stGCL GAT autoencoder. GEMMs on tensor cores (bf16 split hi/lo, fp32 accum).
// N=30000 nodes, E=480000 edges, NH=256.
// ---------------------------------------------------------------------------

#define MAXN 30016
#define MAXE 480000
#define MAXAK 3000   // max K for A operand (features)

typedef __nv_bfloat16 bf16;

// big scratch (device statics; allocation-free rule)
__device__ bf16  g_Ah[(size_t)MAXN * MAXAK];
__device__ bf16  g_Al[(size_t)MAXN * MAXAK];
__device__ float g_Hx[MAXN * 256];
__device__ float g_Hr[MAXN * 256];
__device__ float g_A [MAXN * 512];
__device__ float g_B [MAXN * 512];
__device__ float g_es[MAXN];
__device__ float g_ed[MAXN];
__device__ float g_m [MAXN];
__device__ float g_s [MAXN];
__device__ float g_e [MAXE];
// weight splits: [N][K] layouts
__device__ bf16 g_W1xT_h[256 * 3000];  __device__ bf16 g_W1xT_l[256 * 3000];
__device__ bf16 g_W1rT_h[256 * 2048];  __device__ bf16 g_W1rT_l[256 * 2048];
__device__ bf16 g_W1x_h [3000 * 256];  __device__ bf16 g_W1x_l [3000 * 256];
__device__ bf16 g_W1r_h [2048 * 256];  __device__ bf16 g_W1r_l [2048 * 256];
__device__ bf16 g_W2T_h [64 * 512];    __device__ bf16 g_W2T_l [64 * 512];
__device__ bf16 g_W2_h  [512 * 64];    __device__ bf16 g_W2_l  [512 * 64];

// ---------------------------------------------------------------------------
// split kernels: fp32 -> hi/lo bf16
// ---------------------------------------------------------------------------
__global__ void split_kernel(const float* __restrict__ x,
                             bf16* __restrict__ hi, bf16* __restrict__ lo,
                             size_t n)
{
    size_t i = (size_t)blockIdx.x * blockDim.x + threadIdx.x;
    if (i >= n) return;
    float v = x[i];
    bf16 h = __float2bfloat16(v);
    hi[i] = h;
    lo[i] = __float2bfloat16(v - __bfloat162float(h));
}

// out[c][r] = x[r][c]; out dims [C][R] (transpose + split)
__global__ void tsplit_kernel(const float* __restrict__ x, int R, int C,
                              bf16* __restrict__ hi, bf16* __restrict__ lo)
{
    int i = blockIdx.x * blockDim.x + threadIdx.x;
    if (i >= R * C) return;
    int c = i / R;
    int r = i - c * R;
    float v = x[(size_t)r * C + c];
    bf16 h = __float2bfloat16(v);
    hi[i] = h;
    lo[i] = __float2bfloat16(v - __bfloat162float(h));
}

// ---------------------------------------------------------------------------
// bf16 split GEMM: C[M,N] = (Ah+Al)[M,K] * (Bh+Bl)[N,K]^T, fp32 accum.
// 128x128x32 tiles, 256 threads (8 warps = 2m x 4n), warp tile 64x32.
// cp.async double-buffered. mma.m16n8k16. B loaded with NON-trans ldmatrix
// (B is [N][K] K-contiguous == mma col layout directly).
// ---------------------------------------------------------------------------
#define BM 128
#define BN 128
#define BKT 32
#define SROW 40            // BKT + 8 pad (elems) -> conflict-free ldmatrix
#define TILE_E (BM * SROW) // 5120 elems per matrix per stage
#define SMEM_BYTES (4 * 2 * TILE_E * 2)   // 4 matrices, 2 stages, 2B -> 81920

__device__ __forceinline__ uint32_t s2u(const void* p)
{
    return (uint32_t)__cvta_generic_to_shared(p);
}

__device__ __forceinline__ void cpasync16(uint32_t saddr, const void* gaddr, bool pred)
{
    int sz = pred ? 16 : 0;
    asm volatile("cp.async.cg.shared.global [%0], [%1], 16, %2;\n"
                 :: "r"(saddr), "l"(gaddr), "r"(sz));
}

__device__ __forceinline__ void ldmatrix_x4(uint32_t* r, uint32_t saddr)
{
    asm volatile("ldmatrix.sync.aligned.m8n8.x4.shared.b16 {%0,%1,%2,%3}, [%4];"
                 : "=r"(r[0]), "=r"(r[1]), "=r"(r[2]), "=r"(r[3]) : "r"(saddr));
}

__device__ __forceinline__ void ldmatrix_x2(uint32_t* r, uint32_t saddr)
{
    asm volatile("ldmatrix.sync.aligned.m8n8.x2.shared.b16 {%0,%1}, [%2];"
                 : "=r"(r[0]), "=r"(r[1]) : "r"(saddr));
}

__device__ __forceinline__ void mma16816(float* c, const uint32_t* a, const uint32_t* b)
{
    asm volatile("mma.sync.aligned.m16n8k16.row.col.f32.bf16.bf16.f32 "
                 "{%0,%1,%2,%3}, {%4,%5,%6,%7}, {%8,%9}, {%0,%1,%2,%3};"
                 : "+f"(c[0]), "+f"(c[1]), "+f"(c[2]), "+f"(c[3])
                 : "r"(a[0]), "r"(a[1]), "r"(a[2]), "r"(a[3]), "r"(b[0]), "r"(b[1]));
}

__global__ __launch_bounds__(256) void gemm_mma_kernel(
    const bf16* __restrict__ Ah, const bf16* __restrict__ Al, int lda,
    const bf16* __restrict__ Bh, const bf16* __restrict__ Bl, int ldb,
    float* __restrict__ C, int ldc, int M, int N, int K)
{
    extern __shared__ bf16 smem[];
    // layout per stage: [Ah][Al][Bh][Bl], each TILE_E elems
    const int tid  = threadIdx.x;
    const int lane = tid & 31;
    const int wid  = tid >> 5;
    const int wm   = wid & 1;   // 0..1
    const int wn   = wid >> 1;  // 0..3
    const int bm   = blockIdx.y * BM;
    const int bn   = blockIdx.x * BN;

    bf16* sA[2][2]; bf16* sB[2][2];
    #pragma unroll
    for (int st = 0; st < 2; st++) {
        bf16* base = smem + st * 4 * TILE_E;
        sA[st][0] = base;
        sA[st][1] = base + TILE_E;
        sB[st][0] = base + 2 * TILE_E;
        sB[st][1] = base + 3 * TILE_E;
    }

    float acc[4][4][4];
    #pragma unroll
    for (int i = 0; i < 4; i++)
        #pragma unroll
        for (int j = 0; j < 4; j++)
            #pragma unroll
            for (int k = 0; k < 4; k++) acc[i][j][k] = 0.f;

    const int KT = (K + BKT - 1) / BKT;

    auto load_stage = [&](int st, int k0) {
        #pragma unroll
        for (int j = 0; j < 2; j++) {
            int chunk = tid + j * 256;      // 0..511
            int row = chunk >> 2;
            int cc  = chunk & 3;
            int gk  = k0 + cc * 8;
            // A
            {
                int gr = bm + row;
                bool p = (gr < M) && (gk < K);
                size_t off = (size_t)(p ? gr : 0) * lda + (p ? gk : 0);
                uint32_t sa = s2u(sA[st][0] + row * SROW + cc * 8);
                cpasync16(sa, Ah + off, p);
                uint32_t sa2 = s2u(sA[st][1] + row * SROW + cc * 8);
                cpasync16(sa2, Al + off, p);
            }
            // B
            {
                int gr = bn + row;
                bool p = (gr < N) && (gk < K);
                size_t off = (size_t)(p ? gr : 0) * ldb + (p ? gk : 0);
                uint32_t sb = s2u(sB[st][0] + row * SROW + cc * 8);
                cpasync16(sb, Bh + off, p);
                uint32_t sb2 = s2u(sB[st][1] + row * SROW + cc * 8);
                cpasync16(sb2, Bl + off, p);
            }
        }
    };

    load_stage(0, 0);
    asm volatile("cp.async.commit_group;\n");

    for (int kt = 0; kt < KT; kt++) {
        if (kt + 1 < KT) {
            load_stage((kt + 1) & 1, (kt + 1) * BKT);
            asm volatile("cp.async.commit_group;\n");
            asm volatile("cp.async.wait_group 1;\n");
        } else {
            asm volatile("cp.async.wait_group 0;\n");
        }
        __syncthreads();

        int st = kt & 1;
        #pragma unroll
        for (int kk = 0; kk < BKT; kk += 16) {
            // A fragments (hi and lo)
            uint32_t ah[4][4], al[4][4];
            int arow = wm * 64 + (lane & 15);
            int acol = kk + (lane >> 4) * 8;
            #pragma unroll
            for (int mi = 0; mi < 4; mi++) {
                ldmatrix_x4(ah[mi], s2u(sA[st][0] + (arow + mi * 16) * SROW + acol));
                ldmatrix_x4(al[mi], s2u(sA[st][1] + (arow + mi * 16) * SROW + acol));
            }
            // B fragments: non-trans ldmatrix.x2.
            // lanes 0-7: n-rows 0-7 @ col kk ; lanes 8-15: n-rows 0-7 @ col kk+8
            int brow = wn * 32 + (lane & 7);
            int bcol = kk + ((lane >> 3) & 1) * 8;
            uint32_t bb[4][2];
            // Bh: terms Ah*Bh and Al*Bh
            #pragma unroll
            for (int ni = 0; ni < 4; ni++)
                ldmatrix_x2(bb[ni], s2u(sB[st][0] + (brow + ni * 8) * SROW + bcol));
            #pragma unroll
            for (int mi = 0; mi < 4; mi++)
                #pragma unroll
                for (int ni = 0; ni < 4; ni++) {
                    mma16816(acc[mi][ni], ah[mi], bb[ni]);
                    mma16816(acc[mi][ni], al[mi], bb[ni]);
                }
            // Bl: term Ah*Bl
            #pragma unroll
            for (int ni = 0; ni < 4; ni++)
                ldmatrix_x2(bb[ni], s2u(sB[st][1] + (brow + ni * 8) * SROW + bcol));
            #pragma unroll
            for (int mi = 0; mi < 4; mi++)
                #pragma unroll
                for (int ni = 0; ni < 4; ni++)
                    mma16816(acc[mi][ni], ah[mi], bb[ni]);
        }
        __syncthreads();
    }

    // epilogue: guarded float2 stores (cols even; even col => 8B aligned)
    const int group = lane >> 2;
    const int tig   = lane & 3;
    #pragma unroll
    for (int mi = 0; mi < 4; mi++) {
        #pragma unroll
        for (int ni = 0; ni < 4; ni++) {
            int col = bn + wn * 32 + ni * 8 + tig * 2;
            if (col >= N) continue;
            int r0 = bm + wm * 64 + mi * 16 + group;
            if (r0 < M) {
                float2 v = make_float2(acc[mi][ni][0], acc[mi][ni][1]);
                *(float2*)&C[(size_t)r0 * ldc + col] = v;
            }
            int r1 = r0 + 8;
            if (r1 < M) {
                float2 v = make_float2(acc[mi][ni][2], acc[mi][ni][3]);
                *(float2*)&C[(size_t)r1 * ldc + col] = v;
            }
        }
    }
}

// ---------------------------------------------------------------------------
// Attention helpers
// ---------------------------------------------------------------------------
__global__ void dots_kernel(const float* __restrict__ H, int ld, int D,
                            const float* __restrict__ asrc,
                            const float* __restrict__ adst,
                            const int* __restrict__ p,
                            float* __restrict__ es, float* __restrict__ ed, int N)
{
    int warp = (blockIdx.x * blockDim.x + threadIdx.x) >> 5;
    int lane = threadIdx.x & 31;
    if (warp >= N) return;
    int pi = p ? p[warp] : warp;
    const float* h = H + (size_t)pi * ld;
    float s1 = 0.f, s2 = 0.f;
    for (int d = lane; d < D; d += 32) {
        float v = h[d];
        s1 += v * asrc[d];
        s2 += v * adst[d];
    }
    #pragma unroll
    for (int o = 16; o; o >>= 1) {
        s1 += __shfl_xor_sync(0xffffffffu, s1, o);
        s2 += __shfl_xor_sync(0xffffffffu, s2, o);
    }
    if (lane == 0) { es[warp] = s1; ed[warp] = s2; }
}

__global__ void init_ms_kernel(float* m, float* s, int N)
{
    int i = blockIdx.x * blockDim.x + threadIdx.x;
    if (i < N) { m[i] = -INFINITY; s[i] = 0.f; }
}

__device__ __forceinline__ void atomicMaxFloat(float* addr, float val)
{
    if (val >= 0.f)
        atomicMax((int*)addr, __float_as_int(val));
    else
        atomicMin((unsigned int*)addr, __float_as_uint(val));
}

__global__ void edge_max_kernel(const float* __restrict__ es,
                                const float* __restrict__ ed,
                                const int* __restrict__ src,
                                const int* __restrict__ dst,
                                float* __restrict__ e, float* __restrict__ m, int E)
{
    int i = blockIdx.x * blockDim.x + threadIdx.x;
    if (i >= E) return;
    float v = es[src[i]] + ed[dst[i]];
    v = (v >= 0.f) ? v : 0.2f * v;
    e[i] = v;
    atomicMaxFloat(&m[dst[i]], v);
}

__global__ void edge_exp_kernel(const float* __restrict__ m,
                                const int* __restrict__ dst,
                                float* __restrict__ e, float* __restrict__ s, int E)
{
    int i = blockIdx.x * blockDim.x + threadIdx.x;
    if (i >= E) return;
    float ex = expf(e[i] - m[dst[i]]);
    e[i] = ex;
    atomicAdd(&s[dst[i]], ex);
}

__global__ void edge_aggr_kernel(const float* __restrict__ H, int ld,
                                 const int* __restrict__ p,
                                 const int* __restrict__ src,
                                 const int* __restrict__ dst,
                                 const float* __restrict__ ex,
                                 const float* __restrict__ s,
                                 float* __restrict__ out, int ldout, int coloff,
                                 int D, int E)
{
    int warp = (blockIdx.x * blockDim.x + threadIdx.x) >> 5;
    int lane = threadIdx.x & 31;
    if (warp >= E) return;
    int sd = dst[warp];
    int ss = src[warp];
    int ps = p ? p[ss] : ss;
    float alpha = ex[warp] / (s[sd] + 1e-16f);
    const float* hrow = H + (size_t)ps * ld;
    float* orow = out + (size_t)sd * ldout + coloff;
    for (int d = lane; d < D; d += 32)
        atomicAdd(&orow[d], hrow[d] * alpha);
}

__global__ void elu_kernel(float* buf, size_t n)
{
    size_t i = (size_t)blockIdx.x * blockDim.x + threadIdx.x;
    if (i >= n) return;
    float x = buf[i];
    buf[i] = (x > 0.f) ? x : expm1f(x);
}

__global__ void summary_kernel(const float* __restrict__ h2, int N, int C,
                               float* __restrict__ out)
{
    int c = blockIdx.x;
    float acc = 0.f;
    for (int r = threadIdx.x; r < N; r += blockDim.x)
        acc += h2[(size_t)r * C + c];
    __shared__ float sh[256];
    sh[threadIdx.x] = acc;
    __syncthreads();
    for (int o = 128; o; o >>= 1) {
        if (threadIdx.x < o) sh[threadIdx.x] += sh[threadIdx.x + o];
        __syncthreads();
    }
    if (threadIdx.x == 0)
        out[c] = 1.f / (1.f + expf(-sh[0] / (float)N));
}

// ---------------------------------------------------------------------------
// Host side
// ---------------------------------------------------------------------------
static void gemm_mma(const bf16* Ah, const bf16* Al, int lda,
                     const bf16* Bh, const bf16* Bl, int ldb,
                     float* C, int ldc, int M, int N, int K)
{
    dim3 grid((N + BN - 1) / BN, (M + BM - 1) / BM);
    gemm_mma_kernel<<<grid, 256, SMEM_BYTES>>>(Ah, Al, lda, Bh, Bl, ldb,
                                               C, ldc, M, N, K);
}

static void split(const float* x, bf16* hi, bf16* lo, size_t n)
{
    split_kernel<<<(unsigned)((n + 255) / 256), 256>>>(x, hi, lo, n);
}

static void run_attn(const float* H, int ld, int D,
                     const float* asrc, const float* adst, const int* p,
                     const int* src, const int* dst, int N, int E,
                     float* es, float* ed, float* m, float* s, float* ebuf,
                     float* out, int ldout, int coloff)
{
    dots_kernel<<<(N + 7) / 8, 256>>>(H, ld, D, asrc, adst, p, es, ed, N);
    init_ms_kernel<<<(N + 255) / 256, 256>>>(m, s, N);
    edge_max_kernel<<<(E + 255) / 256, 256>>>(es, ed, src, dst, ebuf, m, E);
    edge_exp_kernel<<<(E + 255) / 256, 256>>>(m, dst, ebuf, s, E);
    edge_aggr_kernel<<<(E + 7) / 8, 256>>>(H, ld, p, src, dst, ebuf, s,
                                           out, ldout, coloff, D, E);
}

extern "C" void kernel_launch(void* const* d_in, const int* in_sizes, int n_in,
                              void* d_out, int out_size)
{
    const float* features = (const float*)d_in[0];
    const float* imf      = (const float*)d_in[1];
    const float* W1x      = (const float*)d_in[2];
    const float* a1x_src  = (const float*)d_in[3];
    const float* a1x_dst  = (const float*)d_in[4];
    const float* W1r      = (const float*)d_in[5];
    const float* a1r_src  = (const float*)d_in[6];
    const float* a1r_dst  = (const float*)d_in[7];
    const float* W2       = (const float*)d_in[8];
    const float* a3_src   = (const float*)d_in[9];
    const float* a3_dst   = (const float*)d_in[10];
    const int*   edge     = (const int*)d_in[11];
    const int*   perm     = (const int*)d_in[12];

    const int NH  = in_sizes[3];              // 256
    const int INX = in_sizes[2] / NH;         // 3000
    const int INR = in_sizes[5] / NH;         // 2048
    const int OUT = in_sizes[8] / (2 * NH);   // 64
    const int N   = in_sizes[0] / INX;        // 30000
    const int E   = in_sizes[11] / 2;         // 480000
    const int D2  = 2 * NH;                   // 512

    const int* src = edge;
    const int* dst = edge + E;

    cudaFuncSetAttribute(gemm_mma_kernel,
                         cudaFuncAttributeMaxDynamicSharedMemorySize, SMEM_BYTES);

    bf16 *Ah, *Al;
    bf16 *W1xT_h, *W1xT_l, *W1rT_h, *W1rT_l, *W1x_h, *W1x_l, *W1r_h, *W1r_l;
    bf16 *W2T_h, *W2T_l, *W2_h, *W2_l;
    float *Hx, *Hr, *Abuf, *Bbuf, *es, *ed, *m, *s, *ebuf;
    cudaGetSymbolAddress((void**)&Ah,   g_Ah);
    cudaGetSymbolAddress((void**)&Al,   g_Al);
    cudaGetSymbolAddress((void**)&Hx,   g_Hx);
    cudaGetSymbolAddress((void**)&Hr,   g_Hr);
    cudaGetSymbolAddress((void**)&Abuf, g_A);
    cudaGetSymbolAddress((void**)&Bbuf, g_B);
    cudaGetSymbolAddress((void**)&es,   g_es);
    cudaGetSymbolAddress((void**)&ed,   g_ed);
    cudaGetSymbolAddress((void**)&m,    g_m);
    cudaGetSymbolAddress((void**)&s,    g_s);
    cudaGetSymbolAddress((void**)&ebuf, g_e);
    cudaGetSymbolAddress((void**)&W1xT_h, g_W1xT_h);
    cudaGetSymbolAddress((void**)&W1xT_l, g_W1xT_l);
    cudaGetSymbolAddress((void**)&W1rT_h, g_W1rT_h);
    cudaGetSymbolAddress((void**)&W1rT_l, g_W1rT_l);
    cudaGetSymbolAddress((void**)&W1x_h,  g_W1x_h);
    cudaGetSymbolAddress((void**)&W1x_l,  g_W1x_l);
    cudaGetSymbolAddress((void**)&W1r_h,  g_W1r_h);
    cudaGetSymbolAddress((void**)&W1r_l,  g_W1r_l);
    cudaGetSymbolAddress((void**)&W2T_h,  g_W2T_h);
    cudaGetSymbolAddress((void**)&W2T_l,  g_W2T_l);
    cudaGetSymbolAddress((void**)&W2_h,   g_W2_h);
    cudaGetSymbolAddress((void**)&W2_l,   g_W2_l);

    float* out = (float*)d_out;
    float* o_h2   = out;
    float* o_h4x  = o_h2   + (size_t)N * OUT;
    float* o_h4r  = o_h4x  + (size_t)N * INX;
    float* o_rh2  = o_h4r  + (size_t)N * INR;
    float* o_rh4x = o_rh2  + (size_t)N * OUT;
    float* o_rh4r = o_rh4x + (size_t)N * INX;
    float* o_sum  = o_rh4r + (size_t)N * INR;

    // ---- weight preps (split + transposed split) ----
    tsplit_kernel<<<(INX * NH + 255) / 256, 256>>>(W1x, INX, NH, W1xT_h, W1xT_l); // [NH][INX]
    tsplit_kernel<<<(INR * NH + 255) / 256, 256>>>(W1r, INR, NH, W1rT_h, W1rT_l); // [NH][INR]
    tsplit_kernel<<<(D2 * OUT + 255) / 256, 256>>>(W2, D2, OUT, W2T_h, W2T_l);    // [OUT][D2]
    split(W1x, W1x_h, W1x_l, (size_t)INX * NH);   // [INX][NH]
    split(W1r, W1r_h, W1r_l, (size_t)INR * NH);   // [INR][NH]
    split(W2,  W2_h,  W2_l,  (size_t)D2 * OUT);   // [D2][OUT]

    // ---- shared pre-attention features: Hx = features@W1x, Hr = imf@W1r ----
    split(features, Ah, Al, (size_t)N * INX);
    gemm_mma(Ah, Al, INX, W1xT_h, W1xT_l, INX, Hx, NH, N, NH, INX);
    split(imf, Ah, Al, (size_t)N * INR);
    gemm_mma(Ah, Al, INR, W1rT_h, W1rT_l, INR, Hr, NH, N, NH, INR);

    for (int path = 0; path < 2; path++) {
        const int* p = path ? perm : nullptr;
        float* oh2  = path ? o_rh2  : o_h2;
        float* oh4x = path ? o_rh4x : o_h4x;
        float* oh4r = path ? o_rh4r : o_h4r;

        // --- encode: two GAT layers into concat buffer, elu, then @ W2 ---
        cudaMemsetAsync(Abuf, 0, (size_t)N * D2 * sizeof(float));
        run_attn(Hx, NH, NH, a1x_src, a1x_dst, p, src, dst, N, E,
                 es, ed, m, s, ebuf, Abuf, D2, 0);
        run_attn(Hr, NH, NH, a1r_src, a1r_dst, p, src, dst, N, E,
                 es, ed, m, s, ebuf, Abuf, D2, NH);
        {
            size_t n = (size_t)N * D2;
            elu_kernel<<<(unsigned)((n + 255) / 256), 256>>>(Abuf, n);
        }
        split(Abuf, Ah, Al, (size_t)N * D2);
        gemm_mma(Ah, Al, D2, W2T_h, W2T_l, D2, oh2, OUT, N, OUT, D2);

        // --- decode: hd = h2 @ W2^T (B = W2 [D2][OUT], already [n][k]) ---
        split(oh2, Ah, Al, (size_t)N * OUT);
        gemm_mma(Ah, Al, OUT, W2_h, W2_l, OUT, Abuf, D2, N, D2, OUT);

        cudaMemsetAsync(Bbuf, 0, (size_t)N * D2 * sizeof(float));
        run_attn(Abuf, D2, D2, a3_src, a3_dst, nullptr, src, dst, N, E,
                 es, ed, m, s, ebuf, Bbuf, D2, 0);
        {
            size_t n = (size_t)N * D2;
            elu_kernel<<<(unsigned)((n + 255) / 256), 256>>>(Bbuf, n);
        }
        // project back: oh4x = h3[:, :NH] @ W1x^T, oh4r = h3[:, NH:] @ W1r^T
        split(Bbuf, Ah, Al, (size_t)N * D2);
        gemm_mma(Ah,      Al,      D2, W1x_h, W1x_l, NH, oh4x, INX, N, INX, NH);
        gemm_mma(Ah + NH, Al + NH, D2, W1r_h, W1r_l, NH, oh4r, INR, N, INR, NH);
    }

    summary_kernel<<<OUT, 256>>>(o_h2, N, OUT, o_sum);
}

// round 9
// speedup vs baseline: 1.0025x; 1.0025x over previous
#include <cuda_runtime.h>
#include <cuda_bf16.h>
#include <math.h>
#include <stdint.h>

// ---------------------------------------------------------------------------
// stGCL GAT autoencoder. GEMMs on tensor cores (bf16 split hi/lo, fp32 accum).
// N=30000 nodes, E=480000 edges, NH=256.
// ---------------------------------------------------------------------------

#define MAXN 30016
#define MAXE 480000
#define MAXAK 3000   // max K for A operand (features)

typedef __nv_bfloat16 bf16;

// big scratch (device statics; allocation-free rule)
__device__ bf16  g_Ah[(size_t)MAXN * MAXAK];
__device__ bf16  g_Al[(size_t)MAXN * MAXAK];
__device__ float g_Hx[MAXN * 256];
__device__ float g_Hr[MAXN * 256];
__device__ float g_A [MAXN * 512];
__device__ float g_B [MAXN * 512];
__device__ float g_es[MAXN];
__device__ float g_ed[MAXN];
__device__ float g_m [MAXN];
__device__ float g_s [MAXN];
__device__ float g_e [MAXE];
// weight splits: [N][K] layouts
__device__ bf16 g_W1xT_h[256 * 3000];  __device__ bf16 g_W1xT_l[256 * 3000];
__device__ bf16 g_W1rT_h[256 * 2048];  __device__ bf16 g_W1rT_l[256 * 2048];
__device__ bf16 g_W1x_h [3000 * 256];  __device__ bf16 g_W1x_l [3000 * 256];
__device__ bf16 g_W1r_h [2048 * 256];  __device__ bf16 g_W1r_l [2048 * 256];
__device__ bf16 g_W2T_h [64 * 512];    __device__ bf16 g_W2T_l [64 * 512];
__device__ bf16 g_W2_h  [512 * 64];    __device__ bf16 g_W2_l  [512 * 64];

// ---------------------------------------------------------------------------
// split kernels: fp32 -> hi/lo bf16
// ---------------------------------------------------------------------------
__global__ void split_kernel(const float* __restrict__ x,
                             bf16* __restrict__ hi, bf16* __restrict__ lo,
                             size_t n)
{
    size_t i = (size_t)blockIdx.x * blockDim.x + threadIdx.x;
    if (i >= n) return;
    float v = x[i];
    bf16 h = __float2bfloat16(v);
    hi[i] = h;
    lo[i] = __float2bfloat16(v - __bfloat162float(h));
}

// out[c][r] = x[r][c]; out dims [C][R] (transpose + split)
__global__ void tsplit_kernel(const float* __restrict__ x, int R, int C,
                              bf16* __restrict__ hi, bf16* __restrict__ lo)
{
    int i = blockIdx.x * blockDim.x + threadIdx.x;
    if (i >= R * C) return;
    int c = i / R;
    int r = i - c * R;
    float v = x[(size_t)r * C + c];
    bf16 h = __float2bfloat16(v);
    hi[i] = h;
    lo[i] = __float2bfloat16(v - __bfloat162float(h));
}

// ---------------------------------------------------------------------------
// bf16 split GEMM: C[M,N] = (Ah+Al)[M,K] * (Bh+Bl)[N,K]^T, fp32 accum.
// 128x128x32 tiles, 256 threads (8 warps = 2m x 4n), warp tile 64x32.
// cp.async double-buffered. mma.m16n8k16. B loaded with NON-trans ldmatrix
// (B is [N][K] K-contiguous == mma col layout directly).
// ---------------------------------------------------------------------------
#define BM 128
#define BN 128
#define BKT 32
#define SROW 40            // BKT + 8 pad (elems) -> conflict-free ldmatrix
#define TILE_E (BM * SROW) // 5120 elems per matrix per stage
#define SMEM_BYTES (4 * 2 * TILE_E * 2)   // 4 matrices, 2 stages, 2B -> 81920

__device__ __forceinline__ uint32_t s2u(const void* p)
{
    return (uint32_t)__cvta_generic_to_shared(p);
}

__device__ __forceinline__ void cpasync16(uint32_t saddr, const void* gaddr, bool pred)
{
    int sz = pred ? 16 : 0;
    asm volatile("cp.async.cg.shared.global [%0], [%1], 16, %2;\n"
                 :: "r"(saddr), "l"(gaddr), "r"(sz));
}

__device__ __forceinline__ void ldmatrix_x4(uint32_t* r, uint32_t saddr)
{
    asm volatile("ldmatrix.sync.aligned.m8n8.x4.shared.b16 {%0,%1,%2,%3}, [%4];"
                 : "=r"(r[0]), "=r"(r[1]), "=r"(r[2]), "=r"(r[3]) : "r"(saddr));
}

__device__ __forceinline__ void ldmatrix_x2(uint32_t* r, uint32_t saddr)
{
    asm volatile("ldmatrix.sync.aligned.m8n8.x2.shared.b16 {%0,%1}, [%2];"
                 : "=r"(r[0]), "=r"(r[1]) : "r"(saddr));
}

__device__ __forceinline__ void mma16816(float* c, const uint32_t* a, const uint32_t* b)
{
    asm volatile("mma.sync.aligned.m16n8k16.row.col.f32.bf16.bf16.f32 "
                 "{%0,%1,%2,%3}, {%4,%5,%6,%7}, {%8,%9}, {%0,%1,%2,%3};"
                 : "+f"(c[0]), "+f"(c[1]), "+f"(c[2]), "+f"(c[3])
                 : "r"(a[0]), "r"(a[1]), "r"(a[2]), "r"(a[3]), "r"(b[0]), "r"(b[1]));
}

__global__ __launch_bounds__(256) void gemm_mma_kernel(
    const bf16* __restrict__ Ah, const bf16* __restrict__ Al, int lda,
    const bf16* __restrict__ Bh, const bf16* __restrict__ Bl, int ldb,
    float* __restrict__ C, int ldc, int M, int N, int K)
{
    extern __shared__ bf16 smem[];
    // layout per stage: [Ah][Al][Bh][Bl], each TILE_E elems
    const int tid  = threadIdx.x;
    const int lane = tid & 31;
    const int wid  = tid >> 5;
    const int wm   = wid & 1;   // 0..1
    const int wn   = wid >> 1;  // 0..3
    const int bm   = blockIdx.y * BM;
    const int bn   = blockIdx.x * BN;

    bf16* sA[2][2]; bf16* sB[2][2];
    #pragma unroll
    for (int st = 0; st < 2; st++) {
        bf16* base = smem + st * 4 * TILE_E;
        sA[st][0] = base;
        sA[st][1] = base + TILE_E;
        sB[st][0] = base + 2 * TILE_E;
        sB[st][1] = base + 3 * TILE_E;
    }

    float acc[4][4][4];
    #pragma unroll
    for (int i = 0; i < 4; i++)
        #pragma unroll
        for (int j = 0; j < 4; j++)
            #pragma unroll
            for (int k = 0; k < 4; k++) acc[i][j][k] = 0.f;

    const int KT = (K + BKT - 1) / BKT;

    auto load_stage = [&](int st, int k0) {
        #pragma unroll
        for (int j = 0; j < 2; j++) {
            int chunk = tid + j * 256;      // 0..511
            int row = chunk >> 2;
            int cc  = chunk & 3;
            int gk  = k0 + cc * 8;
            // A
            {
                int gr = bm + row;
                bool p = (gr < M) && (gk < K);
                size_t off = (size_t)(p ? gr : 0) * lda + (p ? gk : 0);
                uint32_t sa = s2u(sA[st][0] + row * SROW + cc * 8);
                cpasync16(sa, Ah + off, p);
                uint32_t sa2 = s2u(sA[st][1] + row * SROW + cc * 8);
                cpasync16(sa2, Al + off, p);
            }
            // B
            {
                int gr = bn + row;
                bool p = (gr < N) && (gk < K);
                size_t off = (size_t)(p ? gr : 0) * ldb + (p ? gk : 0);
                uint32_t sb = s2u(sB[st][0] + row * SROW + cc * 8);
                cpasync16(sb, Bh + off, p);
                uint32_t sb2 = s2u(sB[st][1] + row * SROW + cc * 8);
                cpasync16(sb2, Bl + off, p);
            }
        }
    };

    load_stage(0, 0);
    asm volatile("cp.async.commit_group;\n");

    for (int kt = 0; kt < KT; kt++) {
        if (kt + 1 < KT) {
            load_stage((kt + 1) & 1, (kt + 1) * BKT);
            asm volatile("cp.async.commit_group;\n");
            asm volatile("cp.async.wait_group 1;\n");
        } else {
            asm volatile("cp.async.wait_group 0;\n");
        }
        __syncthreads();

        int st = kt & 1;
        #pragma unroll
        for (int kk = 0; kk < BKT; kk += 16) {
            // A fragments (hi and lo)
            uint32_t ah[4][4], al[4][4];
            int arow = wm * 64 + (lane & 15);
            int acol = kk + (lane >> 4) * 8;
            #pragma unroll
            for (int mi = 0; mi < 4; mi++) {
                ldmatrix_x4(ah[mi], s2u(sA[st][0] + (arow + mi * 16) * SROW + acol));
                ldmatrix_x4(al[mi], s2u(sA[st][1] + (arow + mi * 16) * SROW + acol));
            }
            // B fragments: non-trans ldmatrix.x2.
            // lanes 0-7: n-rows 0-7 @ col kk ; lanes 8-15: n-rows 0-7 @ col kk+8
            int brow = wn * 32 + (lane & 7);
            int bcol = kk + ((lane >> 3) & 1) * 8;
            uint32_t bb[4][2];
            // Bh: terms Ah*Bh and Al*Bh
            #pragma unroll
            for (int ni = 0; ni < 4; ni++)
                ldmatrix_x2(bb[ni], s2u(sB[st][0] + (brow + ni * 8) * SROW + bcol));
            #pragma unroll
            for (int mi = 0; mi < 4; mi++)
                #pragma unroll
                for (int ni = 0; ni < 4; ni++) {
                    mma16816(acc[mi][ni], ah[mi], bb[ni]);
                    mma16816(acc[mi][ni], al[mi], bb[ni]);
                }
            // Bl: term Ah*Bl
            #pragma unroll
            for (int ni = 0; ni < 4; ni++)
                ldmatrix_x2(bb[ni], s2u(sB[st][1] + (brow + ni * 8) * SROW + bcol));
            #pragma unroll
            for (int mi = 0; mi < 4; mi++)
                #pragma unroll
                for (int ni = 0; ni < 4; ni++)
                    mma16816(acc[mi][ni], ah[mi], bb[ni]);
        }
        __syncthreads();
    }

    // epilogue: guarded float2 stores (cols even; even col => 8B aligned)
    const int group = lane >> 2;
    const int tig   = lane & 3;
    #pragma unroll
    for (int mi = 0; mi < 4; mi++) {
        #pragma unroll
        for (int ni = 0; ni < 4; ni++) {
            int col = bn + wn * 32 + ni * 8 + tig * 2;
            if (col >= N) continue;
            int r0 = bm + wm * 64 + mi * 16 + group;
            if (r0 < M) {
                float2 v = make_float2(acc[mi][ni][0], acc[mi][ni][1]);
                *(float2*)&C[(size_t)r0 * ldc + col] = v;
            }
            int r1 = r0 + 8;
            if (r1 < M) {
                float2 v = make_float2(acc[mi][ni][2], acc[mi][ni][3]);
                *(float2*)&C[(size_t)r1 * ldc + col] = v;
            }
        }
    }
}

// ---------------------------------------------------------------------------
// Attention helpers
// ---------------------------------------------------------------------------
__global__ void dots_kernel(const float* __restrict__ H, int ld, int D,
                            const float* __restrict__ asrc,
                            const float* __restrict__ adst,
                            const int* __restrict__ p,
                            float* __restrict__ es, float* __restrict__ ed, int N)
{
    int warp = (blockIdx.x * blockDim.x + threadIdx.x) >> 5;
    int lane = threadIdx.x & 31;
    if (warp >= N) return;
    int pi = p ? p[warp] : warp;
    const float* h = H + (size_t)pi * ld;
    float s1 = 0.f, s2 = 0.f;
    for (int d = lane; d < D; d += 32) {
        float v = h[d];
        s1 += v * asrc[d];
        s2 += v * adst[d];
    }
    #pragma unroll
    for (int o = 16; o; o >>= 1) {
        s1 += __shfl_xor_sync(0xffffffffu, s1, o);
        s2 += __shfl_xor_sync(0xffffffffu, s2, o);
    }
    if (lane == 0) { es[warp] = s1; ed[warp] = s2; }
}

__global__ void init_ms_kernel(float* m, float* s, int N)
{
    int i = blockIdx.x * blockDim.x + threadIdx.x;
    if (i < N) { m[i] = -INFINITY; s[i] = 0.f; }
}

__device__ __forceinline__ void atomicMaxFloat(float* addr, float val)
{
    if (val >= 0.f)
        atomicMax((int*)addr, __float_as_int(val));
    else
        atomicMin((unsigned int*)addr, __float_as_uint(val));
}

__global__ void edge_max_kernel(const float* __restrict__ es,
                                const float* __restrict__ ed,
                                const int* __restrict__ src,
                                const int* __restrict__ dst,
                                float* __restrict__ e, float* __restrict__ m, int E)
{
    int i = blockIdx.x * blockDim.x + threadIdx.x;
    if (i >= E) return;
    float v = es[src[i]] + ed[dst[i]];
    v = (v >= 0.f) ? v : 0.2f * v;
    e[i] = v;
    atomicMaxFloat(&m[dst[i]], v);
}

__global__ void edge_exp_kernel(const float* __restrict__ m,
                                const int* __restrict__ dst,
                                float* __restrict__ e, float* __restrict__ s, int E)
{
    int i = blockIdx.x * blockDim.x + threadIdx.x;
    if (i >= E) return;
    float ex = expf(e[i] - m[dst[i]]);
    e[i] = ex;
    atomicAdd(&s[dst[i]], ex);
}

__global__ void edge_aggr_kernel(const float* __restrict__ H, int ld,
                                 const int* __restrict__ p,
                                 const int* __restrict__ src,
                                 const int* __restrict__ dst,
                                 const float* __restrict__ ex,
                                 const float* __restrict__ s,
                                 float* __restrict__ out, int ldout, int coloff,
                                 int D, int E)
{
    int warp = (blockIdx.x * blockDim.x + threadIdx.x) >> 5;
    int lane = threadIdx.x & 31;
    if (warp >= E) return;
    int sd = dst[warp];
    int ss = src[warp];
    int ps = p ? p[ss] : ss;
    float alpha = ex[warp] / (s[sd] + 1e-16f);
    const float* hrow = H + (size_t)ps * ld;
    float* orow = out + (size_t)sd * ldout + coloff;
    for (int d = lane; d < D; d += 32)
        atomicAdd(&orow[d], hrow[d] * alpha);
}

__global__ void elu_kernel(float* buf, size_t n)
{
    size_t i = (size_t)blockIdx.x * blockDim.x + threadIdx.x;
    if (i >= n) return;
    float x = buf[i];
    buf[i] = (x > 0.f) ? x : expm1f(x);
}

__global__ void summary_kernel(const float* __restrict__ h2, int N, int C,
                               float* __restrict__ out)
{
    int c = blockIdx.x;
    float acc = 0.f;
    for (int r = threadIdx.x; r < N; r += blockDim.x)
        acc += h2[(size_t)r * C + c];
    __shared__ float sh[256];
    sh[threadIdx.x] = acc;
    __syncthreads();
    for (int o = 128; o; o >>= 1) {
        if (threadIdx.x < o) sh[threadIdx.x] += sh[threadIdx.x + o];
        __syncthreads();
    }
    if (threadIdx.x == 0)
        out[c] = 1.f / (1.f + expf(-sh[0] / (float)N));
}

// ---------------------------------------------------------------------------
// Host side
// ---------------------------------------------------------------------------
static void gemm_mma(const bf16* Ah, const bf16* Al, int lda,
                     const bf16* Bh, const bf16* Bl, int ldb,
                     float* C, int ldc, int M, int N, int K)
{
    dim3 grid((N + BN - 1) / BN, (M + BM - 1) / BM);
    gemm_mma_kernel<<<grid, 256, SMEM_BYTES>>>(Ah, Al, lda, Bh, Bl, ldb,
                                               C, ldc, M, N, K);
}

static void split(const float* x, bf16* hi, bf16* lo, size_t n)
{
    split_kernel<<<(unsigned)((n + 255) / 256), 256>>>(x, hi, lo, n);
}

static void run_attn(const float* H, int ld, int D,
                     const float* asrc, const float* adst, const int* p,
                     const int* src, const int* dst, int N, int E,
                     float* es, float* ed, float* m, float* s, float* ebuf,
                     float* out, int ldout, int coloff)
{
    dots_kernel<<<(N + 7) / 8, 256>>>(H, ld, D, asrc, adst, p, es, ed, N);
    init_ms_kernel<<<(N + 255) / 256, 256>>>(m, s, N);
    edge_max_kernel<<<(E + 255) / 256, 256>>>(es, ed, src, dst, ebuf, m, E);
    edge_exp_kernel<<<(E + 255) / 256, 256>>>(m, dst, ebuf, s, E);
    edge_aggr_kernel<<<(E + 7) / 8, 256>>>(H, ld, p, src, dst, ebuf, s,
                                           out, ldout, coloff, D, E);
}

extern "C" void kernel_launch(void* const* d_in, const int* in_sizes, int n_in,
                              void* d_out, int out_size)
{
    const float* features = (const float*)d_in[0];
    const float* imf      = (const float*)d_in[1];
    const float* W1x      = (const float*)d_in[2];
    const float* a1x_src  = (const float*)d_in[3];
    const float* a1x_dst  = (const float*)d_in[4];
    const float* W1r      = (const float*)d_in[5];
    const float* a1r_src  = (const float*)d_in[6];
    const float* a1r_dst  = (const float*)d_in[7];
    const float* W2       = (const float*)d_in[8];
    const float* a3_src   = (const float*)d_in[9];
    const float* a3_dst   = (const float*)d_in[10];
    const int*   edge     = (const int*)d_in[11];
    const int*   perm     = (const int*)d_in[12];

    const int NH  = in_sizes[3];              // 256
    const int INX = in_sizes[2] / NH;         // 3000
    const int INR = in_sizes[5] / NH;         // 2048
    const int OUT = in_sizes[8] / (2 * NH);   // 64
    const int N   = in_sizes[0] / INX;        // 30000
    const int E   = in_sizes[11] / 2;         // 480000
    const int D2  = 2 * NH;                   // 512

    const int* src = edge;
    const int* dst = edge + E;

    cudaFuncSetAttribute(gemm_mma_kernel,
                         cudaFuncAttributeMaxDynamicSharedMemorySize, SMEM_BYTES);

    bf16 *Ah, *Al;
    bf16 *W1xT_h, *W1xT_l, *W1rT_h, *W1rT_l, *W1x_h, *W1x_l, *W1r_h, *W1r_l;
    bf16 *W2T_h, *W2T_l, *W2_h, *W2_l;
    float *Hx, *Hr, *Abuf, *Bbuf, *es, *ed, *m, *s, *ebuf;
    cudaGetSymbolAddress((void**)&Ah,   g_Ah);
    cudaGetSymbolAddress((void**)&Al,   g_Al);
    cudaGetSymbolAddress((void**)&Hx,   g_Hx);
    cudaGetSymbolAddress((void**)&Hr,   g_Hr);
    cudaGetSymbolAddress((void**)&Abuf, g_A);
    cudaGetSymbolAddress((void**)&Bbuf, g_B);
    cudaGetSymbolAddress((void**)&es,   g_es);
    cudaGetSymbolAddress((void**)&ed,   g_ed);
    cudaGetSymbolAddress((void**)&m,    g_m);
    cudaGetSymbolAddress((void**)&s,    g_s);
    cudaGetSymbolAddress((void**)&ebuf, g_e);
    cudaGetSymbolAddress((void**)&W1xT_h, g_W1xT_h);
    cudaGetSymbolAddress((void**)&W1xT_l, g_W1xT_l);
    cudaGetSymbolAddress((void**)&W1rT_h, g_W1rT_h);
    cudaGetSymbolAddress((void**)&W1rT_l, g_W1rT_l);
    cudaGetSymbolAddress((void**)&W1x_h,  g_W1x_h);
    cudaGetSymbolAddress((void**)&W1x_l,  g_W1x_l);
    cudaGetSymbolAddress((void**)&W1r_h,  g_W1r_h);
    cudaGetSymbolAddress((void**)&W1r_l,  g_W1r_l);
    cudaGetSymbolAddress((void**)&W2T_h,  g_W2T_h);
    cudaGetSymbolAddress((void**)&W2T_l,  g_W2T_l);
    cudaGetSymbolAddress((void**)&W2_h,   g_W2_h);
    cudaGetSymbolAddress((void**)&W2_l,   g_W2_l);

    float* out = (float*)d_out;
    float* o_h2   = out;
    float* o_h4x  = o_h2   + (size_t)N * OUT;
    float* o_h4r  = o_h4x  + (size_t)N * INX;
    float* o_rh2  = o_h4r  + (size_t)N * INR;
    float* o_rh4x = o_rh2  + (size_t)N * OUT;
    float* o_rh4r = o_rh4x + (size_t)N * INX;
    float* o_sum  = o_rh4r + (size_t)N * INR;

    // ---- weight preps (split + transposed split) ----
    tsplit_kernel<<<(INX * NH + 255) / 256, 256>>>(W1x, INX, NH, W1xT_h, W1xT_l); // [NH][INX]
    tsplit_kernel<<<(INR * NH + 255) / 256, 256>>>(W1r, INR, NH, W1rT_h, W1rT_l); // [NH][INR]
    tsplit_kernel<<<(D2 * OUT + 255) / 256, 256>>>(W2, D2, OUT, W2T_h, W2T_l);    // [OUT][D2]
    split(W1x, W1x_h, W1x_l, (size_t)INX * NH);   // [INX][NH]
    split(W1r, W1r_h, W1r_l, (size_t)INR * NH);   // [INR][NH]
    split(W2,  W2_h,  W2_l,  (size_t)D2 * OUT);   // [D2][OUT]

    // ---- shared pre-attention features: Hx = features@W1x, Hr = imf@W1r ----
    split(features, Ah, Al, (size_t)N * INX);
    gemm_mma(Ah, Al, INX, W1xT_h, W1xT_l, INX, Hx, NH, N, NH, INX);
    split(imf, Ah, Al, (size_t)N * INR);
    gemm_mma(Ah, Al, INR, W1rT_h, W1rT_l, INR, Hr, NH, N, NH, INR);

    for (int path = 0; path < 2; path++) {
        const int* p = path ? perm : nullptr;
        float* oh2  = path ? o_rh2  : o_h2;
        float* oh4x = path ? o_rh4x : o_h4x;
        float* oh4r = path ? o_rh4r : o_h4r;

        // --- encode: two GAT layers into concat buffer, elu, then @ W2 ---
        cudaMemsetAsync(Abuf, 0, (size_t)N * D2 * sizeof(float));
        run_attn(Hx, NH, NH, a1x_src, a1x_dst, p, src, dst, N, E,
                 es, ed, m, s, ebuf, Abuf, D2, 0);
        run_attn(Hr, NH, NH, a1r_src, a1r_dst, p, src, dst, N, E,
                 es, ed, m, s, ebuf, Abuf, D2, NH);
        {
            size_t n = (size_t)N * D2;
            elu_kernel<<<(unsigned)((n + 255) / 256), 256>>>(Abuf, n);
        }
        split(Abuf, Ah, Al, (size_t)N * D2);
        gemm_mma(Ah, Al, D2, W2T_h, W2T_l, D2, oh2, OUT, N, OUT, D2);

        // --- decode: hd = h2 @ W2^T (B = W2 [D2][OUT], already [n][k]) ---
        split(oh2, Ah, Al, (size_t)N * OUT);
        gemm_mma(Ah, Al, OUT, W2_h, W2_l, OUT, Abuf, D2, N, D2, OUT);

        cudaMemsetAsync(Bbuf, 0, (size_t)N * D2 * sizeof(float));
        run_attn(Abuf, D2, D2, a3_src, a3_dst, nullptr, src, dst, N, E,
                 es, ed, m, s, ebuf, Bbuf, D2, 0);
        {
            size_t n = (size_t)N * D2;
            elu_kernel<<<(unsigned)((n + 255) / 256), 256>>>(Bbuf, n);
        }
        // project back: oh4x = h3[:, :NH] @ W1x^T, oh4r = h3[:, NH:] @ W1r^T
        split(Bbuf, Ah, Al, (size_t)N * D2);
        gemm_mma(Ah,      Al,      D2, W1x_h, W1x_l, NH, oh4x, INX, N, INX, NH);
        gemm_mma(Ah + NH, Al + NH, D2, W1r_h, W1r_l, NH, oh4r, INR, N, INR, NH);
    }

    summary_kernel<<<OUT, 256>>>(o_h2, N, OUT, o_sum);
}

// round 11
// speedup vs baseline: 1.1344x; 1.1315x over previous
#include <cuda_runtime.h>
#include <cuda_bf16.h>
#include <math.h>
#include <stdint.h>

// ---------------------------------------------------------------------------
// stGCL GAT autoencoder. GEMMs on tensor cores (bf16 split hi/lo, fp32 accum).
// Aggregation is CSR gather-based (no float atomics).
// N=30000 nodes, E=480000 edges, NH=256.
// ---------------------------------------------------------------------------

#define MAXN 30016
#define MAXE 480000
#define MAXAK 3000   // max K for A operand (features)

typedef __nv_bfloat16 bf16;

// big scratch (device statics; allocation-free rule)
__device__ bf16  g_Ah[(size_t)MAXN * MAXAK];
__device__ bf16  g_Al[(size_t)MAXN * MAXAK];
__device__ float g_Hx[MAXN * 256];
__device__ float g_Hr[MAXN * 256];
__device__ float g_A [MAXN * 512];
__device__ float g_es[MAXN];
__device__ float g_ed[MAXN];
// CSR by dst
__device__ int g_roff[MAXN + 1];
__device__ int g_cnt [MAXN];
__device__ int g_cur [MAXN];
__device__ int g_rsrc[MAXE];
// weight splits: [N][K] layouts
__device__ bf16 g_W1xT_h[256 * 3000];  __device__ bf16 g_W1xT_l[256 * 3000];
__device__ bf16 g_W1rT_h[256 * 2048];  __device__ bf16 g_W1rT_l[256 * 2048];
__device__ bf16 g_W1x_h [3000 * 256];  __device__ bf16 g_W1x_l [3000 * 256];
__device__ bf16 g_W1r_h [2048 * 256];  __device__ bf16 g_W1r_l [2048 * 256];
__device__ bf16 g_W2T_h [64 * 512];    __device__ bf16 g_W2T_l [64 * 512];
__device__ bf16 g_W2_h  [512 * 64];    __device__ bf16 g_W2_l  [512 * 64];

// ---------------------------------------------------------------------------
// split kernels: fp32 -> hi/lo bf16
// ---------------------------------------------------------------------------
__global__ void split_kernel(const float* __restrict__ x,
                             bf16* __restrict__ hi, bf16* __restrict__ lo,
                             size_t n)
{
    size_t i = (size_t)blockIdx.x * blockDim.x + threadIdx.x;
    if (i >= n) return;
    float v = x[i];
    bf16 h = __float2bfloat16(v);
    hi[i] = h;
    lo[i] = __float2bfloat16(v - __bfloat162float(h));
}

// out[c][r] = x[r][c]; out dims [C][R] (transpose + split)
__global__ void tsplit_kernel(const float* __restrict__ x, int R, int C,
                              bf16* __restrict__ hi, bf16* __restrict__ lo)
{
    int i = blockIdx.x * blockDim.x + threadIdx.x;
    if (i >= R * C) return;
    int c = i / R;
    int r = i - c * R;
    float v = x[(size_t)r * C + c];
    bf16 h = __float2bfloat16(v);
    hi[i] = h;
    lo[i] = __float2bfloat16(v - __bfloat162float(h));
}

// ---------------------------------------------------------------------------
// bf16 split GEMM (proven in best kernel): C[M,N] = (Ah+Al)[M,K]*(Bh+Bl)[N,K]^T
// ---------------------------------------------------------------------------
#define BM 128
#define BN 128
#define BKT 32
#define SROW 40            // BKT + 8 pad (elems) -> conflict-free ldmatrix
#define TILE_E (BM * SROW)
#define SMEM_BYTES (4 * 2 * TILE_E * 2)

__device__ __forceinline__ uint32_t s2u(const void* p)
{
    return (uint32_t)__cvta_generic_to_shared(p);
}

__device__ __forceinline__ void cpasync16(uint32_t saddr, const void* gaddr, bool pred)
{
    int sz = pred ? 16 : 0;
    asm volatile("cp.async.cg.shared.global [%0], [%1], 16, %2;\n"
                 :: "r"(saddr), "l"(gaddr), "r"(sz));
}

__device__ __forceinline__ void ldmatrix_x4(uint32_t* r, uint32_t saddr)
{
    asm volatile("ldmatrix.sync.aligned.m8n8.x4.shared.b16 {%0,%1,%2,%3}, [%4];"
                 : "=r"(r[0]), "=r"(r[1]), "=r"(r[2]), "=r"(r[3]) : "r"(saddr));
}

__device__ __forceinline__ void ldmatrix_x2(uint32_t* r, uint32_t saddr)
{
    asm volatile("ldmatrix.sync.aligned.m8n8.x2.shared.b16 {%0,%1}, [%2];"
                 : "=r"(r[0]), "=r"(r[1]) : "r"(saddr));
}

__device__ __forceinline__ void mma16816(float* c, const uint32_t* a, const uint32_t* b)
{
    asm volatile("mma.sync.aligned.m16n8k16.row.col.f32.bf16.bf16.f32 "
                 "{%0,%1,%2,%3}, {%4,%5,%6,%7}, {%8,%9}, {%0,%1,%2,%3};"
                 : "+f"(c[0]), "+f"(c[1]), "+f"(c[2]), "+f"(c[3])
                 : "r"(a[0]), "r"(a[1]), "r"(a[2]), "r"(a[3]), "r"(b[0]), "r"(b[1]));
}

__global__ __launch_bounds__(256) void gemm_mma_kernel(
    const bf16* __restrict__ Ah, const bf16* __restrict__ Al, int lda,
    const bf16* __restrict__ Bh, const bf16* __restrict__ Bl, int ldb,
    float* __restrict__ C, int ldc, int M, int N, int K)
{
    extern __shared__ bf16 smem[];
    const int tid  = threadIdx.x;
    const int lane = tid & 31;
    const int wid  = tid >> 5;
    const int wm   = wid & 1;
    const int wn   = wid >> 1;
    const int bm   = blockIdx.y * BM;
    const int bn   = blockIdx.x * BN;

    bf16* sA[2][2]; bf16* sB[2][2];
    #pragma unroll
    for (int st = 0; st < 2; st++) {
        bf16* base = smem + st * 4 * TILE_E;
        sA[st][0] = base;
        sA[st][1] = base + TILE_E;
        sB[st][0] = base + 2 * TILE_E;
        sB[st][1] = base + 3 * TILE_E;
    }

    float acc[4][4][4];
    #pragma unroll
    for (int i = 0; i < 4; i++)
        #pragma unroll
        for (int j = 0; j < 4; j++)
            #pragma unroll
            for (int k = 0; k < 4; k++) acc[i][j][k] = 0.f;

    const int KT = (K + BKT - 1) / BKT;

    auto load_stage = [&](int st, int k0) {
        #pragma unroll
        for (int j = 0; j < 2; j++) {
            int chunk = tid + j * 256;
            int row = chunk >> 2;
            int cc  = chunk & 3;
            int gk  = k0 + cc * 8;
            {
                int gr = bm + row;
                bool p = (gr < M) && (gk < K);
                size_t off = (size_t)(p ? gr : 0) * lda + (p ? gk : 0);
                cpasync16(s2u(sA[st][0] + row * SROW + cc * 8), Ah + off, p);
                cpasync16(s2u(sA[st][1] + row * SROW + cc * 8), Al + off, p);
            }
            {
                int gr = bn + row;
                bool p = (gr < N) && (gk < K);
                size_t off = (size_t)(p ? gr : 0) * ldb + (p ? gk : 0);
                cpasync16(s2u(sB[st][0] + row * SROW + cc * 8), Bh + off, p);
                cpasync16(s2u(sB[st][1] + row * SROW + cc * 8), Bl + off, p);
            }
        }
    };

    load_stage(0, 0);
    asm volatile("cp.async.commit_group;\n");

    for (int kt = 0; kt < KT; kt++) {
        if (kt + 1 < KT) {
            load_stage((kt + 1) & 1, (kt + 1) * BKT);
            asm volatile("cp.async.commit_group;\n");
            asm volatile("cp.async.wait_group 1;\n");
        } else {
            asm volatile("cp.async.wait_group 0;\n");
        }
        __syncthreads();

        int st = kt & 1;
        #pragma unroll
        for (int kk = 0; kk < BKT; kk += 16) {
            uint32_t ah[4][4], al[4][4];
            int arow = wm * 64 + (lane & 15);
            int acol = kk + (lane >> 4) * 8;
            #pragma unroll
            for (int mi = 0; mi < 4; mi++) {
                ldmatrix_x4(ah[mi], s2u(sA[st][0] + (arow + mi * 16) * SROW + acol));
                ldmatrix_x4(al[mi], s2u(sA[st][1] + (arow + mi * 16) * SROW + acol));
            }
            int brow = wn * 32 + (lane & 7);
            int bcol = kk + ((lane >> 3) & 1) * 8;
            uint32_t bb[4][2];
            #pragma unroll
            for (int ni = 0; ni < 4; ni++)
                ldmatrix_x2(bb[ni], s2u(sB[st][0] + (brow + ni * 8) * SROW + bcol));
            #pragma unroll
            for (int mi = 0; mi < 4; mi++)
                #pragma unroll
                for (int ni = 0; ni < 4; ni++) {
                    mma16816(acc[mi][ni], ah[mi], bb[ni]);
                    mma16816(acc[mi][ni], al[mi], bb[ni]);
                }
            #pragma unroll
            for (int ni = 0; ni < 4; ni++)
                ldmatrix_x2(bb[ni], s2u(sB[st][1] + (brow + ni * 8) * SROW + bcol));
            #pragma unroll
            for (int mi = 0; mi < 4; mi++)
                #pragma unroll
                for (int ni = 0; ni < 4; ni++)
                    mma16816(acc[mi][ni], ah[mi], bb[ni]);
        }
        __syncthreads();
    }

    const int group = lane >> 2;
    const int tig   = lane & 3;
    #pragma unroll
    for (int mi = 0; mi < 4; mi++) {
        #pragma unroll
        for (int ni = 0; ni < 4; ni++) {
            int col = bn + wn * 32 + ni * 8 + tig * 2;
            if (col >= N) continue;
            int r0 = bm + wm * 64 + mi * 16 + group;
            if (r0 < M) {
                float2 v = make_float2(acc[mi][ni][0], acc[mi][ni][1]);
                *(float2*)&C[(size_t)r0 * ldc + col] = v;
            }
            int r1 = r0 + 8;
            if (r1 < M) {
                float2 v = make_float2(acc[mi][ni][2], acc[mi][ni][3]);
                *(float2*)&C[(size_t)r1 * ldc + col] = v;
            }
        }
    }
}

// ---------------------------------------------------------------------------
// CSR build (per launch; graph shared by all 6 attention calls)
// ---------------------------------------------------------------------------
__global__ void zero_cnt_kernel(int* cnt, int N)
{
    int i = blockIdx.x * blockDim.x + threadIdx.x;
    if (i < N) cnt[i] = 0;
}

__global__ void count_kernel(const int* __restrict__ dst, int* cnt, int E)
{
    int i = blockIdx.x * blockDim.x + threadIdx.x;
    if (i < E) atomicAdd(&cnt[dst[i]], 1);
}

// single-block exclusive scan; also initializes cur[] = roff[]
__global__ void scan_kernel(const int* __restrict__ cnt,
                            int* __restrict__ roff, int* __restrict__ cur, int N)
{
    __shared__ int ssum[1024];
    int t = threadIdx.x;
    int per = (N + 1023) / 1024;
    int b = t * per;
    int loc = 0;
    for (int i = 0; i < per; i++)
        if (b + i < N) loc += cnt[b + i];
    ssum[t] = loc;
    __syncthreads();
    for (int o = 1; o < 1024; o <<= 1) {
        int v = (t >= o) ? ssum[t - o] : 0;
        __syncthreads();
        ssum[t] += v;
        __syncthreads();
    }
    int run = (t == 0) ? 0 : ssum[t - 1];
    for (int i = 0; i < per; i++) {
        if (b + i < N) {
            roff[b + i] = run;
            cur[b + i]  = run;
            run += cnt[b + i];
        }
    }
    if (t == 1023) roff[N] = ssum[1023];
}

__global__ void fill_kernel(const int* __restrict__ src,
                            const int* __restrict__ dst,
                            int* __restrict__ cur, int* __restrict__ rsrc, int E)
{
    int i = blockIdx.x * blockDim.x + threadIdx.x;
    if (i >= E) return;
    int pos = atomicAdd(&cur[dst[i]], 1);
    rsrc[pos] = src[i];
}

// ---------------------------------------------------------------------------
// Attention
// ---------------------------------------------------------------------------
// es[i] = dot(H[p[i]], asrc), ed[i] = dot(H[p[i]], adst). One warp per node.
__global__ void dots_kernel(const float* __restrict__ H, int ld, int D,
                            const float* __restrict__ asrc,
                            const float* __restrict__ adst,
                            const int* __restrict__ p,
                            float* __restrict__ es, float* __restrict__ ed, int N)
{
    int warp = (blockIdx.x * blockDim.x + threadIdx.x) >> 5;
    int lane = threadIdx.x & 31;
    if (warp >= N) return;
    int pi = p ? p[warp] : warp;
    const float* h = H + (size_t)pi * ld;
    float s1 = 0.f, s2 = 0.f;
    for (int d = lane; d < D; d += 32) {
        float v = h[d];
        s1 += v * asrc[d];
        s2 += v * adst[d];
    }
    #pragma unroll
    for (int o = 16; o; o >>= 1) {
        s1 += __shfl_xor_sync(0xffffffffu, s1, o);
        s2 += __shfl_xor_sync(0xffffffffu, s2, o);
    }
    if (lane == 0) { es[warp] = s1; ed[warp] = s2; }
}

// Fused per-dst-node softmax + aggregation + optional ELU + optional bf16
// hi/lo split. block = 256 threads; NCH = D/256 (1 or 2) channels per thread.
#define ACHUNK 64
template <int NCH, bool ELU>
__global__ __launch_bounds__(256) void csr_attn_kernel(
    const float* __restrict__ H, int ldh,
    const int* __restrict__ p,
    const float* __restrict__ es, const float* __restrict__ ed,
    const int* __restrict__ roff, const int* __restrict__ rsrc,
    float* __restrict__ outf,
    bf16* __restrict__ outh, bf16* __restrict__ outl,
    int ldo, int coloff)
{
    const int node = blockIdx.x;
    const int tid  = threadIdx.x;
    const int lane = tid & 31;
    const int wid  = tid >> 5;
    const int beg = roff[node];
    const int deg = roff[node + 1] - beg;

    __shared__ float s_w[ACHUNK];
    __shared__ int   s_src[ACHUNK];
    __shared__ float s_ms[2];

    const float edv = ed[node];

    // phase A (warp 0): segment max and sum
    if (wid == 0) {
        float m = -INFINITY;
        for (int j = lane; j < deg; j += 32) {
            float e = es[rsrc[beg + j]] + edv;
            e = (e >= 0.f) ? e : 0.2f * e;
            m = fmaxf(m, e);
        }
        #pragma unroll
        for (int o = 16; o; o >>= 1) m = fmaxf(m, __shfl_xor_sync(0xffffffffu, m, o));
        float ssum = 0.f;
        for (int j = lane; j < deg; j += 32) {
            float e = es[rsrc[beg + j]] + edv;
            e = (e >= 0.f) ? e : 0.2f * e;
            ssum += __expf(e - m);
        }
        #pragma unroll
        for (int o = 16; o; o >>= 1) ssum += __shfl_xor_sync(0xffffffffu, ssum, o);
        if (lane == 0) { s_ms[0] = m; s_ms[1] = ssum; }
    }
    __syncthreads();
    const float m    = s_ms[0];
    const float invs = 1.f / (s_ms[1] + 1e-16f);

    float acc0 = 0.f, acc1 = 0.f;
    for (int c0 = 0; c0 < deg; c0 += ACHUNK) {
        int cl = min(ACHUNK, deg - c0);
        if (tid < cl) {
            int sidx = rsrc[beg + c0 + tid];
            float e = es[sidx] + edv;
            e = (e >= 0.f) ? e : 0.2f * e;
            s_w[tid]   = __expf(e - m) * invs;
            s_src[tid] = p ? p[sidx] : sidx;
        }
        __syncthreads();
        for (int j = 0; j < cl; j++) {
            const float* hrow = H + (size_t)s_src[j] * ldh;
            float w = s_w[j];
            acc0 += w * hrow[tid];
            if (NCH == 2) acc1 += w * hrow[tid + 256];
        }
        __syncthreads();
    }

    if (ELU) {
        acc0 = (acc0 > 0.f) ? acc0 : expm1f(acc0);
        if (NCH == 2) acc1 = (acc1 > 0.f) ? acc1 : expm1f(acc1);
    }
    size_t base = (size_t)node * ldo + coloff;
    if (outf) {
        outf[base + tid] = acc0;
        if (NCH == 2) outf[base + tid + 256] = acc1;
    }
    if (outh) {
        bf16 h0 = __float2bfloat16(acc0);
        outh[base + tid] = h0;
        outl[base + tid] = __float2bfloat16(acc0 - __bfloat162float(h0));
        if (NCH == 2) {
            bf16 h1 = __float2bfloat16(acc1);
            outh[base + tid + 256] = h1;
            outl[base + tid + 256] = __float2bfloat16(acc1 - __bfloat162float(h1));
        }
    }
}

__global__ void summary_kernel(const float* __restrict__ h2, int N, int C,
                               float* __restrict__ out)
{
    int c = blockIdx.x;
    float acc = 0.f;
    for (int r = threadIdx.x; r < N; r += blockDim.x)
        acc += h2[(size_t)r * C + c];
    __shared__ float sh[256];
    sh[threadIdx.x] = acc;
    __syncthreads();
    for (int o = 128; o; o >>= 1) {
        if (threadIdx.x < o) sh[threadIdx.x] += sh[threadIdx.x + o];
        __syncthreads();
    }
    if (threadIdx.x == 0)
        out[c] = 1.f / (1.f + expf(-sh[0] / (float)N));
}

// ---------------------------------------------------------------------------
// Host side
// ---------------------------------------------------------------------------
static void gemm_mma(const bf16* Ah, const bf16* Al, int lda,
                     const bf16* Bh, const bf16* Bl, int ldb,
                     float* C, int ldc, int M, int N, int K)
{
    dim3 grid((N + BN - 1) / BN, (M + BM - 1) / BM);
    gemm_mma_kernel<<<grid, 256, SMEM_BYTES>>>(Ah, Al, lda, Bh, Bl, ldb,
                                               C, ldc, M, N, K);
}

static void split(const float* x, bf16* hi, bf16* lo, size_t n)
{
    split_kernel<<<(unsigned)((n + 255) / 256), 256>>>(x, hi, lo, n);
}

extern "C" void kernel_launch(void* const* d_in, const int* in_sizes, int n_in,
                              void* d_out, int out_size)
{
    const float* features = (const float*)d_in[0];
    const float* imf      = (const float*)d_in[1];
    const float* W1x      = (const float*)d_in[2];
    const float* a1x_src  = (const float*)d_in[3];
    const float* a1x_dst  = (const float*)d_in[4];
    const float* W1r      = (const float*)d_in[5];
    const float* a1r_src  = (const float*)d_in[6];
    const float* a1r_dst  = (const float*)d_in[7];
    const float* W2       = (const float*)d_in[8];
    const float* a3_src   = (const float*)d_in[9];
    const float* a3_dst   = (const float*)d_in[10];
    const int*   edge     = (const int*)d_in[11];
    const int*   perm     = (const int*)d_in[12];

    const int NH  = in_sizes[3];              // 256
    const int INX = in_sizes[2] / NH;         // 3000
    const int INR = in_sizes[5] / NH;         // 2048
    const int OUT = in_sizes[8] / (2 * NH);   // 64
    const int N   = in_sizes[0] / INX;        // 30000
    const int E   = in_sizes[11] / 2;         // 480000
    const int D2  = 2 * NH;                   // 512

    const int* src = edge;
    const int* dst = edge + E;

    cudaFuncSetAttribute(gemm_mma_kernel,
                         cudaFuncAttributeMaxDynamicSharedMemorySize, SMEM_BYTES);

    bf16 *Ah, *Al;
    bf16 *W1xT_h, *W1xT_l, *W1rT_h, *W1rT_l, *W1x_h, *W1x_l, *W1r_h, *W1r_l;
    bf16 *W2T_h, *W2T_l, *W2_h, *W2_l;
    float *Hx, *Hr, *Abuf, *es, *ed;
    int *roff, *cnt, *cur, *rsrc;
    cudaGetSymbolAddress((void**)&Ah,   g_Ah);
    cudaGetSymbolAddress((void**)&Al,   g_Al);
    cudaGetSymbolAddress((void**)&Hx,   g_Hx);
    cudaGetSymbolAddress((void**)&Hr,   g_Hr);
    cudaGetSymbolAddress((void**)&Abuf, g_A);
    cudaGetSymbolAddress((void**)&es,   g_es);
    cudaGetSymbolAddress((void**)&ed,   g_ed);
    cudaGetSymbolAddress((void**)&roff, g_roff);
    cudaGetSymbolAddress((void**)&cnt,  g_cnt);
    cudaGetSymbolAddress((void**)&cur,  g_cur);
    cudaGetSymbolAddress((void**)&rsrc, g_rsrc);
    cudaGetSymbolAddress((void**)&W1xT_h, g_W1xT_h);
    cudaGetSymbolAddress((void**)&W1xT_l, g_W1xT_l);
    cudaGetSymbolAddress((void**)&W1rT_h, g_W1rT_h);
    cudaGetSymbolAddress((void**)&W1rT_l, g_W1rT_l);
    cudaGetSymbolAddress((void**)&W1x_h,  g_W1x_h);
    cudaGetSymbolAddress((void**)&W1x_l,  g_W1x_l);
    cudaGetSymbolAddress((void**)&W1r_h,  g_W1r_h);
    cudaGetSymbolAddress((void**)&W1r_l,  g_W1r_l);
    cudaGetSymbolAddress((void**)&W2T_h,  g_W2T_h);
    cudaGetSymbolAddress((void**)&W2T_l,  g_W2T_l);
    cudaGetSymbolAddress((void**)&W2_h,   g_W2_h);
    cudaGetSymbolAddress((void**)&W2_l,   g_W2_l);

    float* out = (float*)d_out;
    float* o_h2   = out;
    float* o_h4x  = o_h2   + (size_t)N * OUT;
    float* o_h4r  = o_h4x  + (size_t)N * INX;
    float* o_rh2  = o_h4r  + (size_t)N * INR;
    float* o_rh4x = o_rh2  + (size_t)N * OUT;
    float* o_rh4r = o_rh4x + (size_t)N * INX;
    float* o_sum  = o_rh4r + (size_t)N * INR;

    // ---- CSR build (graph shared by all attention calls) ----
    zero_cnt_kernel<<<(N + 255) / 256, 256>>>(cnt, N);
    count_kernel<<<(E + 255) / 256, 256>>>(dst, cnt, E);
    scan_kernel<<<1, 1024>>>(cnt, roff, cur, N);
    fill_kernel<<<(E + 255) / 256, 256>>>(src, dst, cur, rsrc, E);

    // ---- weight preps (split + transposed split) ----
    tsplit_kernel<<<(INX * NH + 255) / 256, 256>>>(W1x, INX, NH, W1xT_h, W1xT_l);
    tsplit_kernel<<<(INR * NH + 255) / 256, 256>>>(W1r, INR, NH, W1rT_h, W1rT_l);
    tsplit_kernel<<<(D2 * OUT + 255) / 256, 256>>>(W2, D2, OUT, W2T_h, W2T_l);
    split(W1x, W1x_h, W1x_l, (size_t)INX * NH);
    split(W1r, W1r_h, W1r_l, (size_t)INR * NH);
    split(W2,  W2_h,  W2_l,  (size_t)D2 * OUT);

    // ---- shared pre-attention features: Hx = features@W1x, Hr = imf@W1r ----
    split(features, Ah, Al, (size_t)N * INX);
    gemm_mma(Ah, Al, INX, W1xT_h, W1xT_l, INX, Hx, NH, N, NH, INX);
    split(imf, Ah, Al, (size_t)N * INR);
    gemm_mma(Ah, Al, INR, W1rT_h, W1rT_l, INR, Hr, NH, N, NH, INR);

    for (int path = 0; path < 2; path++) {
        const int* p = path ? perm : nullptr;
        float* oh2  = path ? o_rh2  : o_h2;
        float* oh4x = path ? o_rh4x : o_h4x;
        float* oh4r = path ? o_rh4r : o_h4r;

        // --- encode: 2 GAT layers fused(softmax+aggr+elu+split) into Ah/Al ---
        dots_kernel<<<(N + 7) / 8, 256>>>(Hx, NH, NH, a1x_src, a1x_dst, p, es, ed, N);
        csr_attn_kernel<1, true><<<N, 256>>>(Hx, NH, p, es, ed, roff, rsrc,
                                             nullptr, Ah, Al, D2, 0);
        dots_kernel<<<(N + 7) / 8, 256>>>(Hr, NH, NH, a1r_src, a1r_dst, p, es, ed, N);
        csr_attn_kernel<1, true><<<N, 256>>>(Hr, NH, p, es, ed, roff, rsrc,
                                             nullptr, Ah, Al, D2, NH);
        gemm_mma(Ah, Al, D2, W2T_h, W2T_l, D2, oh2, OUT, N, OUT, D2);

        // --- decode: hd = h2 @ W2^T -> GAT(a3) -> elu -> split -> project ---
        split(oh2, Ah, Al, (size_t)N * OUT);
        gemm_mma(Ah, Al, OUT, W2_h, W2_l, OUT, Abuf, D2, N, D2, OUT);

        dots_kernel<<<(N + 7) / 8, 256>>>(Abuf, D2, D2, a3_src, a3_dst, nullptr, es, ed, N);
        csr_attn_kernel<2, true><<<N, 256>>>(Abuf, D2, nullptr, es, ed, roff, rsrc,
                                             nullptr, Ah, Al, D2, 0);

        gemm_mma(Ah,      Al,      D2, W1x_h, W1x_l, NH, oh4x, INX, N, INX, NH);
        gemm_mma(Ah + NH, Al + NH, D2, W1r_h, W1r_l, NH, oh4r, INR, N, INR, NH);
    }

    summary_kernel<<<OUT, 256>>>(o_h2, N, OUT, o_sum);
}

// round 13
// speedup vs baseline: 1.4098x; 1.2428x over previous
#include <cuda_runtime.h>
#include <cuda_bf16.h>
#include <cuda_fp16.h>
#include <math.h>
#include <stdint.h>

// ---------------------------------------------------------------------------
// stGCL GAT autoencoder.
//  - Feature / W2 GEMMs: mma.sync bf16 hi/lo split (3-term), fp32 accum.
//  - Decode projection GEMMs (64% of work, final stage): single-term fp16.
//  - Attention: CSR gather-based softmax+aggregation, fused ELU+convert.
// NOTE: tcgen05 unusable — harness compiles PTX for plain sm_103 target.
// N=30000 nodes, E=480000 edges, NH=256.
// ---------------------------------------------------------------------------

#define MAXN 30016
#define MAXE 480000
#define MAXAK 3000

typedef __nv_bfloat16 bf16;

__device__ bf16  g_Ah[(size_t)MAXN * MAXAK];
__device__ bf16  g_Al[(size_t)MAXN * MAXAK];
__device__ float g_Hx[MAXN * 256];
__device__ float g_Hr[MAXN * 256];
__device__ float g_A [MAXN * 512];
__device__ float g_es[MAXN];
__device__ float g_ed[MAXN];
__device__ int g_roff[MAXN + 1];
__device__ int g_cnt [MAXN];
__device__ int g_cur [MAXN];
__device__ int g_rsrc[MAXE];
// weight buffers
__device__ bf16 g_W1xT_h[256 * 3000];  __device__ bf16 g_W1xT_l[256 * 3000];
__device__ bf16 g_W1rT_h[256 * 2048];  __device__ bf16 g_W1rT_l[256 * 2048];
__device__ __half g_W1x_f16[3000 * 256];
__device__ __half g_W1r_f16[2048 * 256];
__device__ bf16 g_W2T_h [64 * 512];    __device__ bf16 g_W2T_l [64 * 512];
__device__ bf16 g_W2_h  [512 * 64];    __device__ bf16 g_W2_l  [512 * 64];

// ---------------------------------------------------------------------------
// helpers
// ---------------------------------------------------------------------------
__device__ __forceinline__ uint32_t s2u(const void* p)
{
    return (uint32_t)__cvta_generic_to_shared(p);
}

__device__ __forceinline__ void cpasync16(uint32_t saddr, const void* gaddr, bool pred)
{
    int sz = pred ? 16 : 0;
    asm volatile("cp.async.cg.shared.global [%0], [%1], 16, %2;\n"
                 :: "r"(saddr), "l"(gaddr), "r"(sz));
}

__device__ __forceinline__ void ldmatrix_x4(uint32_t* r, uint32_t saddr)
{
    asm volatile("ldmatrix.sync.aligned.m8n8.x4.shared.b16 {%0,%1,%2,%3}, [%4];"
                 : "=r"(r[0]), "=r"(r[1]), "=r"(r[2]), "=r"(r[3]) : "r"(saddr));
}

__device__ __forceinline__ void ldmatrix_x2(uint32_t* r, uint32_t saddr)
{
    asm volatile("ldmatrix.sync.aligned.m8n8.x2.shared.b16 {%0,%1}, [%2];"
                 : "=r"(r[0]), "=r"(r[1]) : "r"(saddr));
}

__device__ __forceinline__ void mma16816_bf(float* c, const uint32_t* a, const uint32_t* b)
{
    asm volatile("mma.sync.aligned.m16n8k16.row.col.f32.bf16.bf16.f32 "
                 "{%0,%1,%2,%3}, {%4,%5,%6,%7}, {%8,%9}, {%0,%1,%2,%3};"
                 : "+f"(c[0]), "+f"(c[1]), "+f"(c[2]), "+f"(c[3])
                 : "r"(a[0]), "r"(a[1]), "r"(a[2]), "r"(a[3]), "r"(b[0]), "r"(b[1]));
}

__device__ __forceinline__ void mma16816_f16(float* c, const uint32_t* a, const uint32_t* b)
{
    asm volatile("mma.sync.aligned.m16n8k16.row.col.f32.f16.f16.f32 "
                 "{%0,%1,%2,%3}, {%4,%5,%6,%7}, {%8,%9}, {%0,%1,%2,%3};"
                 : "+f"(c[0]), "+f"(c[1]), "+f"(c[2]), "+f"(c[3])
                 : "r"(a[0]), "r"(a[1]), "r"(a[2]), "r"(a[3]), "r"(b[0]), "r"(b[1]));
}

// ---------------------------------------------------------------------------
// conversion kernels
// ---------------------------------------------------------------------------
__global__ void split_kernel(const float* __restrict__ x,
                             bf16* __restrict__ hi, bf16* __restrict__ lo,
                             size_t n)
{
    size_t i = (size_t)blockIdx.x * blockDim.x + threadIdx.x;
    if (i >= n) return;
    float v = x[i];
    bf16 h = __float2bfloat16(v);
    hi[i] = h;
    lo[i] = __float2bfloat16(v - __bfloat162float(h));
}

__global__ void tsplit_kernel(const float* __restrict__ x, int R, int C,
                              bf16* __restrict__ hi, bf16* __restrict__ lo)
{
    int i = blockIdx.x * blockDim.x + threadIdx.x;
    if (i >= R * C) return;
    int c = i / R;
    int r = i - c * R;
    float v = x[(size_t)r * C + c];
    bf16 h = __float2bfloat16(v);
    hi[i] = h;
    lo[i] = __float2bfloat16(v - __bfloat162float(h));
}

__global__ void cvt_f16_kernel(const float* __restrict__ x,
                               __half* __restrict__ y, size_t n)
{
    size_t i = (size_t)blockIdx.x * blockDim.x + threadIdx.x;
    if (i < n) y[i] = __float2half(x[i]);
}

// ===========================================================================
// 3-term bf16 split GEMM (proven): C[M,N] = (Ah+Al)[M,K]*(Bh+Bl)[N,K]^T
// ===========================================================================
#define BM 128
#define BN 128
#define BKT 32
#define SROW 40
#define TILE_E (BM * SROW)
#define SMEM_BYTES (4 * 2 * TILE_E * 2)

__global__ __launch_bounds__(256) void gemm_mma_kernel(
    const bf16* __restrict__ Ah, const bf16* __restrict__ Al, int lda,
    const bf16* __restrict__ Bh, const bf16* __restrict__ Bl, int ldb,
    float* __restrict__ C, int ldc, int M, int N, int K)
{
    extern __shared__ bf16 smem[];
    const int tid  = threadIdx.x;
    const int lane = tid & 31;
    const int wid  = tid >> 5;
    const int wm   = wid & 1;
    const int wn   = wid >> 1;
    const int bm   = blockIdx.y * BM;
    const int bn   = blockIdx.x * BN;

    bf16* sA[2][2]; bf16* sB[2][2];
    #pragma unroll
    for (int st = 0; st < 2; st++) {
        bf16* base = smem + st * 4 * TILE_E;
        sA[st][0] = base;
        sA[st][1] = base + TILE_E;
        sB[st][0] = base + 2 * TILE_E;
        sB[st][1] = base + 3 * TILE_E;
    }

    float acc[4][4][4];
    #pragma unroll
    for (int i = 0; i < 4; i++)
        #pragma unroll
        for (int j = 0; j < 4; j++)
            #pragma unroll
            for (int k = 0; k < 4; k++) acc[i][j][k] = 0.f;

    const int KT = (K + BKT - 1) / BKT;

    auto load_stage = [&](int st, int k0) {
        #pragma unroll
        for (int j = 0; j < 2; j++) {
            int chunk = tid + j * 256;
            int row = chunk >> 2;
            int cc  = chunk & 3;
            int gk  = k0 + cc * 8;
            {
                int gr = bm + row;
                bool p = (gr < M) && (gk < K);
                size_t off = (size_t)(p ? gr : 0) * lda + (p ? gk : 0);
                cpasync16(s2u(sA[st][0] + row * SROW + cc * 8), Ah + off, p);
                cpasync16(s2u(sA[st][1] + row * SROW + cc * 8), Al + off, p);
            }
            {
                int gr = bn + row;
                bool p = (gr < N) && (gk < K);
                size_t off = (size_t)(p ? gr : 0) * ldb + (p ? gk : 0);
                cpasync16(s2u(sB[st][0] + row * SROW + cc * 8), Bh + off, p);
                cpasync16(s2u(sB[st][1] + row * SROW + cc * 8), Bl + off, p);
            }
        }
    };

    load_stage(0, 0);
    asm volatile("cp.async.commit_group;\n");

    for (int kt = 0; kt < KT; kt++) {
        if (kt + 1 < KT) {
            load_stage((kt + 1) & 1, (kt + 1) * BKT);
            asm volatile("cp.async.commit_group;\n");
            asm volatile("cp.async.wait_group 1;\n");
        } else {
            asm volatile("cp.async.wait_group 0;\n");
        }
        __syncthreads();

        int st = kt & 1;
        #pragma unroll
        for (int kk = 0; kk < BKT; kk += 16) {
            uint32_t ah[4][4], al[4][4];
            int arow = wm * 64 + (lane & 15);
            int acol = kk + (lane >> 4) * 8;
            #pragma unroll
            for (int mi = 0; mi < 4; mi++) {
                ldmatrix_x4(ah[mi], s2u(sA[st][0] + (arow + mi * 16) * SROW + acol));
                ldmatrix_x4(al[mi], s2u(sA[st][1] + (arow + mi * 16) * SROW + acol));
            }
            int brow = wn * 32 + (lane & 7);
            int bcol = kk + ((lane >> 3) & 1) * 8;
            uint32_t bb[4][2];
            #pragma unroll
            for (int ni = 0; ni < 4; ni++)
                ldmatrix_x2(bb[ni], s2u(sB[st][0] + (brow + ni * 8) * SROW + bcol));
            #pragma unroll
            for (int mi = 0; mi < 4; mi++)
                #pragma unroll
                for (int ni = 0; ni < 4; ni++) {
                    mma16816_bf(acc[mi][ni], ah[mi], bb[ni]);
                    mma16816_bf(acc[mi][ni], al[mi], bb[ni]);
                }
            #pragma unroll
            for (int ni = 0; ni < 4; ni++)
                ldmatrix_x2(bb[ni], s2u(sB[st][1] + (brow + ni * 8) * SROW + bcol));
            #pragma unroll
            for (int mi = 0; mi < 4; mi++)
                #pragma unroll
                for (int ni = 0; ni < 4; ni++)
                    mma16816_bf(acc[mi][ni], ah[mi], bb[ni]);
        }
        __syncthreads();
    }

    const int group = lane >> 2;
    const int tig   = lane & 3;
    #pragma unroll
    for (int mi = 0; mi < 4; mi++) {
        #pragma unroll
        for (int ni = 0; ni < 4; ni++) {
            int col = bn + wn * 32 + ni * 8 + tig * 2;
            if (col >= N) continue;
            int r0 = bm + wm * 64 + mi * 16 + group;
            if (r0 < M) {
                float2 v = make_float2(acc[mi][ni][0], acc[mi][ni][1]);
                *(float2*)&C[(size_t)r0 * ldc + col] = v;
            }
            int r1 = r0 + 8;
            if (r1 < M) {
                float2 v = make_float2(acc[mi][ni][2], acc[mi][ni][3]);
                *(float2*)&C[(size_t)r1 * ldc + col] = v;
            }
        }
    }
}

// ===========================================================================
// single-term fp16 GEMM: C[M,N] = A[M,K] * B[N,K]^T  (final projections)
// Half the smem of the split kernel -> better occupancy.
// ===========================================================================
#define SMEM_F16 (2 * 2 * TILE_E * 2)   // 2 matrices, 2 stages -> 40960 B

__global__ __launch_bounds__(256) void gemm_f16_kernel(
    const __half* __restrict__ A, int lda,
    const __half* __restrict__ B, int ldb,
    float* __restrict__ C, int ldc, int M, int N, int K)
{
    extern __shared__ __half smh[];
    const int tid  = threadIdx.x;
    const int lane = tid & 31;
    const int wid  = tid >> 5;
    const int wm   = wid & 1;
    const int wn   = wid >> 1;
    const int bm   = blockIdx.y * BM;
    const int bn   = blockIdx.x * BN;

    __half* sA[2]; __half* sB[2];
    #pragma unroll
    for (int st = 0; st < 2; st++) {
        __half* base = smh + st * 2 * TILE_E;
        sA[st] = base;
        sB[st] = base + TILE_E;
    }

    float acc[4][4][4];
    #pragma unroll
    for (int i = 0; i < 4; i++)
        #pragma unroll
        for (int j = 0; j < 4; j++)
            #pragma unroll
            for (int k = 0; k < 4; k++) acc[i][j][k] = 0.f;

    const int KT = (K + BKT - 1) / BKT;

    auto load_stage = [&](int st, int k0) {
        #pragma unroll
        for (int j = 0; j < 2; j++) {
            int chunk = tid + j * 256;
            int row = chunk >> 2;
            int cc  = chunk & 3;
            int gk  = k0 + cc * 8;
            {
                int gr = bm + row;
                bool p = (gr < M) && (gk < K);
                size_t off = (size_t)(p ? gr : 0) * lda + (p ? gk : 0);
                cpasync16(s2u(sA[st] + row * SROW + cc * 8), A + off, p);
            }
            {
                int gr = bn + row;
                bool p = (gr < N) && (gk < K);
                size_t off = (size_t)(p ? gr : 0) * ldb + (p ? gk : 0);
                cpasync16(s2u(sB[st] + row * SROW + cc * 8), B + off, p);
            }
        }
    };

    load_stage(0, 0);
    asm volatile("cp.async.commit_group;\n");

    for (int kt = 0; kt < KT; kt++) {
        if (kt + 1 < KT) {
            load_stage((kt + 1) & 1, (kt + 1) * BKT);
            asm volatile("cp.async.commit_group;\n");
            asm volatile("cp.async.wait_group 1;\n");
        } else {
            asm volatile("cp.async.wait_group 0;\n");
        }
        __syncthreads();

        int st = kt & 1;
        #pragma unroll
        for (int kk = 0; kk < BKT; kk += 16) {
            uint32_t af[4][4];
            int arow = wm * 64 + (lane & 15);
            int acol = kk + (lane >> 4) * 8;
            #pragma unroll
            for (int mi = 0; mi < 4; mi++)
                ldmatrix_x4(af[mi], s2u(sA[st] + (arow + mi * 16) * SROW + acol));
            int brow = wn * 32 + (lane & 7);
            int bcol = kk + ((lane >> 3) & 1) * 8;
            uint32_t bb[4][2];
            #pragma unroll
            for (int ni = 0; ni < 4; ni++)
                ldmatrix_x2(bb[ni], s2u(sB[st] + (brow + ni * 8) * SROW + bcol));
            #pragma unroll
            for (int mi = 0; mi < 4; mi++)
                #pragma unroll
                for (int ni = 0; ni < 4; ni++)
                    mma16816_f16(acc[mi][ni], af[mi], bb[ni]);
        }
        __syncthreads();
    }

    const int group = lane >> 2;
    const int tig   = lane & 3;
    #pragma unroll
    for (int mi = 0; mi < 4; mi++) {
        #pragma unroll
        for (int ni = 0; ni < 4; ni++) {
            int col = bn + wn * 32 + ni * 8 + tig * 2;
            if (col >= N) continue;
            int r0 = bm + wm * 64 + mi * 16 + group;
            if (r0 < M) {
                float2 v = make_float2(acc[mi][ni][0], acc[mi][ni][1]);
                *(float2*)&C[(size_t)r0 * ldc + col] = v;
            }
            int r1 = r0 + 8;
            if (r1 < M) {
                float2 v = make_float2(acc[mi][ni][2], acc[mi][ni][3]);
                *(float2*)&C[(size_t)r1 * ldc + col] = v;
            }
        }
    }
}

// ---------------------------------------------------------------------------
// CSR build
// ---------------------------------------------------------------------------
__global__ void zero_cnt_kernel(int* cnt, int N)
{
    int i = blockIdx.x * blockDim.x + threadIdx.x;
    if (i < N) cnt[i] = 0;
}

__global__ void count_kernel(const int* __restrict__ dst, int* cnt, int E)
{
    int i = blockIdx.x * blockDim.x + threadIdx.x;
    if (i < E) atomicAdd(&cnt[dst[i]], 1);
}

__global__ void scan_kernel(const int* __restrict__ cnt,
                            int* __restrict__ roff, int* __restrict__ cur, int N)
{
    __shared__ int ssum[1024];
    int t = threadIdx.x;
    int per = (N + 1023) / 1024;
    int b = t * per;
    int loc = 0;
    for (int i = 0; i < per; i++)
        if (b + i < N) loc += cnt[b + i];
    ssum[t] = loc;
    __syncthreads();
    for (int o = 1; o < 1024; o <<= 1) {
        int v = (t >= o) ? ssum[t - o] : 0;
        __syncthreads();
        ssum[t] += v;
        __syncthreads();
    }
    int run = (t == 0) ? 0 : ssum[t - 1];
    for (int i = 0; i < per; i++) {
        if (b + i < N) {
            roff[b + i] = run;
            cur[b + i]  = run;
            run += cnt[b + i];
        }
    }
    if (t == 1023) roff[N] = ssum[1023];
}

__global__ void fill_kernel(const int* __restrict__ src,
                            const int* __restrict__ dst,
                            int* __restrict__ cur, int* __restrict__ rsrc, int E)
{
    int i = blockIdx.x * blockDim.x + threadIdx.x;
    if (i >= E) return;
    int pos = atomicAdd(&cur[dst[i]], 1);
    rsrc[pos] = src[i];
}

// ---------------------------------------------------------------------------
// Attention
// ---------------------------------------------------------------------------
__global__ void dots_kernel(const float* __restrict__ H, int ld, int D,
                            const float* __restrict__ asrc,
                            const float* __restrict__ adst,
                            const int* __restrict__ p,
                            float* __restrict__ es, float* __restrict__ ed, int N)
{
    int warp = (blockIdx.x * blockDim.x + threadIdx.x) >> 5;
    int lane = threadIdx.x & 31;
    if (warp >= N) return;
    int pi = p ? p[warp] : warp;
    const float* h = H + (size_t)pi * ld;
    float s1 = 0.f, s2 = 0.f;
    for (int d = lane; d < D; d += 32) {
        float v = h[d];
        s1 += v * asrc[d];
        s2 += v * adst[d];
    }
    #pragma unroll
    for (int o = 16; o; o >>= 1) {
        s1 += __shfl_xor_sync(0xffffffffu, s1, o);
        s2 += __shfl_xor_sync(0xffffffffu, s2, o);
    }
    if (lane == 0) { es[warp] = s1; ed[warp] = s2; }
}

// Fused per-node softmax + aggregation + ELU + output convert.
// OMODE: 0 = bf16 hi/lo split pair, 1 = single fp16.
#define ACHUNK 64
template <int NCH, int OMODE>
__global__ __launch_bounds__(256) void csr_attn_kernel(
    const float* __restrict__ H, int ldh,
    const int* __restrict__ p,
    const float* __restrict__ es, const float* __restrict__ ed,
    const int* __restrict__ roff, const int* __restrict__ rsrc,
    bf16* __restrict__ outh, bf16* __restrict__ outl,
    int ldo, int coloff)
{
    const int node = blockIdx.x;
    const int tid  = threadIdx.x;
    const int lane = tid & 31;
    const int wid  = tid >> 5;
    const int beg = roff[node];
    const int deg = roff[node + 1] - beg;

    __shared__ float s_w[ACHUNK];
    __shared__ int   s_src[ACHUNK];
    __shared__ float s_ms[2];

    const float edv = ed[node];

    if (wid == 0) {
        float m = -INFINITY;
        for (int j = lane; j < deg; j += 32) {
            float e = es[rsrc[beg + j]] + edv;
            e = (e >= 0.f) ? e : 0.2f * e;
            m = fmaxf(m, e);
        }
        #pragma unroll
        for (int o = 16; o; o >>= 1) m = fmaxf(m, __shfl_xor_sync(0xffffffffu, m, o));
        float ssum = 0.f;
        for (int j = lane; j < deg; j += 32) {
            float e = es[rsrc[beg + j]] + edv;
            e = (e >= 0.f) ? e : 0.2f * e;
            ssum += __expf(e - m);
        }
        #pragma unroll
        for (int o = 16; o; o >>= 1) ssum += __shfl_xor_sync(0xffffffffu, ssum, o);
        if (lane == 0) { s_ms[0] = m; s_ms[1] = ssum; }
    }
    __syncthreads();
    const float m    = s_ms[0];
    const float invs = 1.f / (s_ms[1] + 1e-16f);

    float acc0 = 0.f, acc1 = 0.f;
    for (int c0 = 0; c0 < deg; c0 += ACHUNK) {
        int cl = min(ACHUNK, deg - c0);
        if (tid < cl) {
            int sidx = rsrc[beg + c0 + tid];
            float e = es[sidx] + edv;
            e = (e >= 0.f) ? e : 0.2f * e;
            s_w[tid]   = __expf(e - m) * invs;
            s_src[tid] = p ? p[sidx] : sidx;
        }
        __syncthreads();
        for (int j = 0; j < cl; j++) {
            const float* hrow = H + (size_t)s_src[j] * ldh;
            float w = s_w[j];
            acc0 += w * hrow[tid];
            if (NCH == 2) acc1 += w * hrow[tid + 256];
        }
        __syncthreads();
    }

    acc0 = (acc0 > 0.f) ? acc0 : expm1f(acc0);
    if (NCH == 2) acc1 = (acc1 > 0.f) ? acc1 : expm1f(acc1);

    size_t base = (size_t)node * ldo + coloff;
    if (OMODE == 0) {
        bf16 h0 = __float2bfloat16(acc0);
        outh[base + tid] = h0;
        outl[base + tid] = __float2bfloat16(acc0 - __bfloat162float(h0));
        if (NCH == 2) {
            bf16 h1 = __float2bfloat16(acc1);
            outh[base + tid + 256] = h1;
            outl[base + tid + 256] = __float2bfloat16(acc1 - __bfloat162float(h1));
        }
    } else {
        __half* oh = (__half*)outh;
        oh[base + tid] = __float2half(acc0);
        if (NCH == 2) oh[base + tid + 256] = __float2half(acc1);
    }
}

__global__ void summary_kernel(const float* __restrict__ h2, int N, int C,
                               float* __restrict__ out)
{
    int c = blockIdx.x;
    float acc = 0.f;
    for (int r = threadIdx.x; r < N; r += blockDim.x)
        acc += h2[(size_t)r * C + c];
    __shared__ float sh[256];
    sh[threadIdx.x] = acc;
    __syncthreads();
    for (int o = 128; o; o >>= 1) {
        if (threadIdx.x < o) sh[threadIdx.x] += sh[threadIdx.x + o];
        __syncthreads();
    }
    if (threadIdx.x == 0)
        out[c] = 1.f / (1.f + expf(-sh[0] / (float)N));
}

// ---------------------------------------------------------------------------
// Host side
// ---------------------------------------------------------------------------
static void gemm_mma(const bf16* Ah, const bf16* Al, int lda,
                     const bf16* Bh, const bf16* Bl, int ldb,
                     float* C, int ldc, int M, int N, int K)
{
    dim3 grid((N + BN - 1) / BN, (M + BM - 1) / BM);
    gemm_mma_kernel<<<grid, 256, SMEM_BYTES>>>(Ah, Al, lda, Bh, Bl, ldb,
                                               C, ldc, M, N, K);
}

static void gemm_f16(const __half* A, int lda, const __half* B, int ldb,
                     float* C, int ldc, int M, int N, int K)
{
    dim3 grid((N + BN - 1) / BN, (M + BM - 1) / BM);
    gemm_f16_kernel<<<grid, 256, SMEM_F16>>>(A, lda, B, ldb, C, ldc, M, N, K);
}

static void split(const float* x, bf16* hi, bf16* lo, size_t n)
{
    split_kernel<<<(unsigned)((n + 255) / 256), 256>>>(x, hi, lo, n);
}

extern "C" void kernel_launch(void* const* d_in, const int* in_sizes, int n_in,
                              void* d_out, int out_size)
{
    const float* features = (const float*)d_in[0];
    const float* imf      = (const float*)d_in[1];
    const float* W1x      = (const float*)d_in[2];
    const float* a1x_src  = (const float*)d_in[3];
    const float* a1x_dst  = (const float*)d_in[4];
    const float* W1r      = (const float*)d_in[5];
    const float* a1r_src  = (const float*)d_in[6];
    const float* a1r_dst  = (const float*)d_in[7];
    const float* W2       = (const float*)d_in[8];
    const float* a3_src   = (const float*)d_in[9];
    const float* a3_dst   = (const float*)d_in[10];
    const int*   edge     = (const int*)d_in[11];
    const int*   perm     = (const int*)d_in[12];

    const int NH  = in_sizes[3];              // 256
    const int INX = in_sizes[2] / NH;         // 3000
    const int INR = in_sizes[5] / NH;         // 2048
    const int OUT = in_sizes[8] / (2 * NH);   // 64
    const int N   = in_sizes[0] / INX;        // 30000
    const int E   = in_sizes[11] / 2;         // 480000
    const int D2  = 2 * NH;                   // 512

    const int* src = edge;
    const int* dst = edge + E;

    cudaFuncSetAttribute(gemm_mma_kernel,
                         cudaFuncAttributeMaxDynamicSharedMemorySize, SMEM_BYTES);
    cudaFuncSetAttribute(gemm_f16_kernel,
                         cudaFuncAttributeMaxDynamicSharedMemorySize, SMEM_F16);

    bf16 *Ah, *Al;
    bf16 *W1xT_h, *W1xT_l, *W1rT_h, *W1rT_l;
    __half *W1x_f16, *W1r_f16;
    bf16 *W2T_h, *W2T_l, *W2_h, *W2_l;
    float *Hx, *Hr, *Abuf, *es, *ed;
    int *roff, *cnt, *cur, *rsrc;
    cudaGetSymbolAddress((void**)&Ah,   g_Ah);
    cudaGetSymbolAddress((void**)&Al,   g_Al);
    cudaGetSymbolAddress((void**)&Hx,   g_Hx);
    cudaGetSymbolAddress((void**)&Hr,   g_Hr);
    cudaGetSymbolAddress((void**)&Abuf, g_A);
    cudaGetSymbolAddress((void**)&es,   g_es);
    cudaGetSymbolAddress((void**)&ed,   g_ed);
    cudaGetSymbolAddress((void**)&roff, g_roff);
    cudaGetSymbolAddress((void**)&cnt,  g_cnt);
    cudaGetSymbolAddress((void**)&cur,  g_cur);
    cudaGetSymbolAddress((void**)&rsrc, g_rsrc);
    cudaGetSymbolAddress((void**)&W1xT_h, g_W1xT_h);
    cudaGetSymbolAddress((void**)&W1xT_l, g_W1xT_l);
    cudaGetSymbolAddress((void**)&W1rT_h, g_W1rT_h);
    cudaGetSymbolAddress((void**)&W1rT_l, g_W1rT_l);
    cudaGetSymbolAddress((void**)&W1x_f16, g_W1x_f16);
    cudaGetSymbolAddress((void**)&W1r_f16, g_W1r_f16);
    cudaGetSymbolAddress((void**)&W2T_h,  g_W2T_h);
    cudaGetSymbolAddress((void**)&W2T_l,  g_W2T_l);
    cudaGetSymbolAddress((void**)&W2_h,   g_W2_h);
    cudaGetSymbolAddress((void**)&W2_l,   g_W2_l);

    float* out = (float*)d_out;
    float* o_h2   = out;
    float* o_h4x  = o_h2   + (size_t)N * OUT;
    float* o_h4r  = o_h4x  + (size_t)N * INX;
    float* o_rh2  = o_h4r  + (size_t)N * INR;
    float* o_rh4x = o_rh2  + (size_t)N * OUT;
    float* o_rh4r = o_rh4x + (size_t)N * INX;
    float* o_sum  = o_rh4r + (size_t)N * INR;

    // ---- CSR build ----
    zero_cnt_kernel<<<(N + 255) / 256, 256>>>(cnt, N);
    count_kernel<<<(E + 255) / 256, 256>>>(dst, cnt, E);
    scan_kernel<<<1, 1024>>>(cnt, roff, cur, N);
    fill_kernel<<<(E + 255) / 256, 256>>>(src, dst, cur, rsrc, E);

    // ---- weight preps ----
    tsplit_kernel<<<(INX * NH + 255) / 256, 256>>>(W1x, INX, NH, W1xT_h, W1xT_l);
    tsplit_kernel<<<(INR * NH + 255) / 256, 256>>>(W1r, INR, NH, W1rT_h, W1rT_l);
    tsplit_kernel<<<(D2 * OUT + 255) / 256, 256>>>(W2, D2, OUT, W2T_h, W2T_l);
    split(W2, W2_h, W2_l, (size_t)D2 * OUT);
    cvt_f16_kernel<<<(INX * NH + 255) / 256, 256>>>(W1x, W1x_f16, (size_t)INX * NH);
    cvt_f16_kernel<<<(INR * NH + 255) / 256, 256>>>(W1r, W1r_f16, (size_t)INR * NH);

    // ---- shared pre-attention features (3-term bf16) ----
    split(features, Ah, Al, (size_t)N * INX);
    gemm_mma(Ah, Al, INX, W1xT_h, W1xT_l, INX, Hx, NH, N, NH, INX);
    split(imf, Ah, Al, (size_t)N * INR);
    gemm_mma(Ah, Al, INR, W1rT_h, W1rT_l, INR, Hr, NH, N, NH, INR);

    for (int path = 0; path < 2; path++) {
        const int* p = path ? perm : nullptr;
        float* oh2  = path ? o_rh2  : o_h2;
        float* oh4x = path ? o_rh4x : o_h4x;
        float* oh4r = path ? o_rh4r : o_h4r;

        // --- encode: GAT layers (bf16 split out) -> @W2 (3-term) ---
        dots_kernel<<<(N + 7) / 8, 256>>>(Hx, NH, NH, a1x_src, a1x_dst, p, es, ed, N);
        csr_attn_kernel<1, 0><<<N, 256>>>(Hx, NH, p, es, ed, roff, rsrc,
                                          Ah, Al, D2, 0);
        dots_kernel<<<(N + 7) / 8, 256>>>(Hr, NH, NH, a1r_src, a1r_dst, p, es, ed, N);
        csr_attn_kernel<1, 0><<<N, 256>>>(Hr, NH, p, es, ed, roff, rsrc,
                                          Ah, Al, D2, NH);
        gemm_mma(Ah, Al, D2, W2T_h, W2T_l, D2, oh2, OUT, N, OUT, D2);

        // --- decode: hd = h2 @ W2^T (3-term), GAT (fp16 out), project (fp16) ---
        split(oh2, Ah, Al, (size_t)N * OUT);
        gemm_mma(Ah, Al, OUT, W2_h, W2_l, OUT, Abuf, D2, N, D2, OUT);

        dots_kernel<<<(N + 7) / 8, 256>>>(Abuf, D2, D2, a3_src, a3_dst, nullptr, es, ed, N);
        csr_attn_kernel<2, 1><<<N, 256>>>(Abuf, D2, nullptr, es, ed, roff, rsrc,
                                          Ah, nullptr, D2, 0);

        const __half* H3 = (const __half*)Ah;
        gemm_f16(H3,      D2, W1x_f16, NH, oh4x, INX, N, INX, NH);
        gemm_f16(H3 + NH, D2, W1r_f16, NH, oh4r, INR, N, INR, NH);
    }

    summary_kernel<<<OUT, 256>>>(o_h2, N, OUT, o_sum);
}

// round 14
// speedup vs baseline: 1.7186x; 1.2190x over previous
#include <cuda_runtime.h>
#include <cuda_bf16.h>
#include <cuda_fp16.h>
#include <math.h>
#include <stdint.h>

// ---------------------------------------------------------------------------
// stGCL GAT autoencoder.
//  - Feature GEMMs + decode projections: single-term fp16 mma.sync.
//  - W2 GEMMs (h2-critical, tiny): bf16 hi/lo 3-term, fp32 accum.
//  - Attention: CSR gather softmax+aggregation, fused ELU+convert.
//  - Perm-path logits via gather identity (no extra dots launches).
// NOTE: tcgen05 unusable — harness compiles for plain sm_103 target.
// ---------------------------------------------------------------------------

#define MAXN 30016
#define MAXE 480000
#define MAXAK 3000

typedef __nv_bfloat16 bf16;

__device__ bf16  g_Ah[(size_t)MAXN * MAXAK];   // also aliased as __half buffer
__device__ bf16  g_Al[(size_t)MAXN * 512];
__device__ float g_Hx[MAXN * 256];
__device__ float g_Hr[MAXN * 256];
__device__ float g_A [MAXN * 512];
__device__ float g_es[MAXN];
__device__ float g_ed[MAXN];
__device__ float g_esx[MAXN];
__device__ float g_edx[MAXN];
__device__ float g_esr[MAXN];
__device__ float g_edr[MAXN];
__device__ int g_roff[MAXN + 1];
__device__ int g_cnt [MAXN];
__device__ int g_cur [MAXN];
__device__ int g_rsrc[MAXE];
// weights
__device__ __half g_W1xT_f16[256 * 3000];   // [NH][INX]
__device__ __half g_W1rT_f16[256 * 2048];   // [NH][INR]
__device__ __half g_W1x_f16 [3000 * 256];   // [INX][NH]
__device__ __half g_W1r_f16 [2048 * 256];   // [INR][NH]
__device__ bf16 g_W2T_h [64 * 512];    __device__ bf16 g_W2T_l [64 * 512];
__device__ bf16 g_W2_h  [512 * 64];    __device__ bf16 g_W2_l  [512 * 64];

// ---------------------------------------------------------------------------
// helpers
// ---------------------------------------------------------------------------
__device__ __forceinline__ uint32_t s2u(const void* p)
{
    return (uint32_t)__cvta_generic_to_shared(p);
}

__device__ __forceinline__ void cpasync16(uint32_t saddr, const void* gaddr, bool pred)
{
    int sz = pred ? 16 : 0;
    asm volatile("cp.async.cg.shared.global [%0], [%1], 16, %2;\n"
                 :: "r"(saddr), "l"(gaddr), "r"(sz));
}

__device__ __forceinline__ void ldmatrix_x4(uint32_t* r, uint32_t saddr)
{
    asm volatile("ldmatrix.sync.aligned.m8n8.x4.shared.b16 {%0,%1,%2,%3}, [%4];"
                 : "=r"(r[0]), "=r"(r[1]), "=r"(r[2]), "=r"(r[3]) : "r"(saddr));
}

__device__ __forceinline__ void ldmatrix_x2(uint32_t* r, uint32_t saddr)
{
    asm volatile("ldmatrix.sync.aligned.m8n8.x2.shared.b16 {%0,%1}, [%2];"
                 : "=r"(r[0]), "=r"(r[1]) : "r"(saddr));
}

__device__ __forceinline__ void mma16816_bf(float* c, const uint32_t* a, const uint32_t* b)
{
    asm volatile("mma.sync.aligned.m16n8k16.row.col.f32.bf16.bf16.f32 "
                 "{%0,%1,%2,%3}, {%4,%5,%6,%7}, {%8,%9}, {%0,%1,%2,%3};"
                 : "+f"(c[0]), "+f"(c[1]), "+f"(c[2]), "+f"(c[3])
                 : "r"(a[0]), "r"(a[1]), "r"(a[2]), "r"(a[3]), "r"(b[0]), "r"(b[1]));
}

__device__ __forceinline__ void mma16816_f16(float* c, const uint32_t* a, const uint32_t* b)
{
    asm volatile("mma.sync.aligned.m16n8k16.row.col.f32.f16.f16.f32 "
                 "{%0,%1,%2,%3}, {%4,%5,%6,%7}, {%8,%9}, {%0,%1,%2,%3};"
                 : "+f"(c[0]), "+f"(c[1]), "+f"(c[2]), "+f"(c[3])
                 : "r"(a[0]), "r"(a[1]), "r"(a[2]), "r"(a[3]), "r"(b[0]), "r"(b[1]));
}

// ---------------------------------------------------------------------------
// conversion kernels
// ---------------------------------------------------------------------------
__global__ void split_kernel(const float* __restrict__ x,
                             bf16* __restrict__ hi, bf16* __restrict__ lo,
                             size_t n)
{
    size_t i = (size_t)blockIdx.x * blockDim.x + threadIdx.x;
    if (i >= n) return;
    float v = x[i];
    bf16 h = __float2bfloat16(v);
    hi[i] = h;
    lo[i] = __float2bfloat16(v - __bfloat162float(h));
}

__global__ void tsplit_kernel(const float* __restrict__ x, int R, int C,
                              bf16* __restrict__ hi, bf16* __restrict__ lo)
{
    int i = blockIdx.x * blockDim.x + threadIdx.x;
    if (i >= R * C) return;
    int c = i / R;
    int r = i - c * R;
    float v = x[(size_t)r * C + c];
    bf16 h = __float2bfloat16(v);
    hi[i] = h;
    lo[i] = __float2bfloat16(v - __bfloat162float(h));
}

__global__ void cvt_f16_kernel(const float* __restrict__ x,
                               __half* __restrict__ y, size_t n)
{
    size_t i = (size_t)blockIdx.x * blockDim.x + threadIdx.x;
    if (i < n) y[i] = __float2half(x[i]);
}

// transpose + fp16: out[c][r] = fp16(x[r][c]), out dims [C][R]
__global__ void tcvt_f16_kernel(const float* __restrict__ x, int R, int C,
                                __half* __restrict__ y)
{
    int i = blockIdx.x * blockDim.x + threadIdx.x;
    if (i >= R * C) return;
    int c = i / R;
    int r = i - c * R;
    y[i] = __float2half(x[(size_t)r * C + c]);
}

// ===========================================================================
// 3-term bf16 split GEMM (proven): C[M,N] = (Ah+Al)[M,K]*(Bh+Bl)[N,K]^T
// ===========================================================================
#define BM 128
#define BN 128
#define BKT 32
#define SROW 40
#define TILE_E (BM * SROW)
#define SMEM_BYTES (4 * 2 * TILE_E * 2)

__global__ __launch_bounds__(256) void gemm_mma_kernel(
    const bf16* __restrict__ Ah, const bf16* __restrict__ Al, int lda,
    const bf16* __restrict__ Bh, const bf16* __restrict__ Bl, int ldb,
    float* __restrict__ C, int ldc, int M, int N, int K)
{
    extern __shared__ bf16 smem[];
    const int tid  = threadIdx.x;
    const int lane = tid & 31;
    const int wid  = tid >> 5;
    const int wm   = wid & 1;
    const int wn   = wid >> 1;
    const int bm   = blockIdx.y * BM;
    const int bn   = blockIdx.x * BN;

    bf16* sA[2][2]; bf16* sB[2][2];
    #pragma unroll
    for (int st = 0; st < 2; st++) {
        bf16* base = smem + st * 4 * TILE_E;
        sA[st][0] = base;
        sA[st][1] = base + TILE_E;
        sB[st][0] = base + 2 * TILE_E;
        sB[st][1] = base + 3 * TILE_E;
    }

    float acc[4][4][4];
    #pragma unroll
    for (int i = 0; i < 4; i++)
        #pragma unroll
        for (int j = 0; j < 4; j++)
            #pragma unroll
            for (int k = 0; k < 4; k++) acc[i][j][k] = 0.f;

    const int KT = (K + BKT - 1) / BKT;

    auto load_stage = [&](int st, int k0) {
        #pragma unroll
        for (int j = 0; j < 2; j++) {
            int chunk = tid + j * 256;
            int row = chunk >> 2;
            int cc  = chunk & 3;
            int gk  = k0 + cc * 8;
            {
                int gr = bm + row;
                bool p = (gr < M) && (gk < K);
                size_t off = (size_t)(p ? gr : 0) * lda + (p ? gk : 0);
                cpasync16(s2u(sA[st][0] + row * SROW + cc * 8), Ah + off, p);
                cpasync16(s2u(sA[st][1] + row * SROW + cc * 8), Al + off, p);
            }
            {
                int gr = bn + row;
                bool p = (gr < N) && (gk < K);
                size_t off = (size_t)(p ? gr : 0) * ldb + (p ? gk : 0);
                cpasync16(s2u(sB[st][0] + row * SROW + cc * 8), Bh + off, p);
                cpasync16(s2u(sB[st][1] + row * SROW + cc * 8), Bl + off, p);
            }
        }
    };

    load_stage(0, 0);
    asm volatile("cp.async.commit_group;\n");

    for (int kt = 0; kt < KT; kt++) {
        if (kt + 1 < KT) {
            load_stage((kt + 1) & 1, (kt + 1) * BKT);
            asm volatile("cp.async.commit_group;\n");
            asm volatile("cp.async.wait_group 1;\n");
        } else {
            asm volatile("cp.async.wait_group 0;\n");
        }
        __syncthreads();

        int st = kt & 1;
        #pragma unroll
        for (int kk = 0; kk < BKT; kk += 16) {
            uint32_t ah[4][4], al[4][4];
            int arow = wm * 64 + (lane & 15);
            int acol = kk + (lane >> 4) * 8;
            #pragma unroll
            for (int mi = 0; mi < 4; mi++) {
                ldmatrix_x4(ah[mi], s2u(sA[st][0] + (arow + mi * 16) * SROW + acol));
                ldmatrix_x4(al[mi], s2u(sA[st][1] + (arow + mi * 16) * SROW + acol));
            }
            int brow = wn * 32 + (lane & 7);
            int bcol = kk + ((lane >> 3) & 1) * 8;
            uint32_t bb[4][2];
            #pragma unroll
            for (int ni = 0; ni < 4; ni++)
                ldmatrix_x2(bb[ni], s2u(sB[st][0] + (brow + ni * 8) * SROW + bcol));
            #pragma unroll
            for (int mi = 0; mi < 4; mi++)
                #pragma unroll
                for (int ni = 0; ni < 4; ni++) {
                    mma16816_bf(acc[mi][ni], ah[mi], bb[ni]);
                    mma16816_bf(acc[mi][ni], al[mi], bb[ni]);
                }
            #pragma unroll
            for (int ni = 0; ni < 4; ni++)
                ldmatrix_x2(bb[ni], s2u(sB[st][1] + (brow + ni * 8) * SROW + bcol));
            #pragma unroll
            for (int mi = 0; mi < 4; mi++)
                #pragma unroll
                for (int ni = 0; ni < 4; ni++)
                    mma16816_bf(acc[mi][ni], ah[mi], bb[ni]);
        }
        __syncthreads();
    }

    const int group = lane >> 2;
    const int tig   = lane & 3;
    #pragma unroll
    for (int mi = 0; mi < 4; mi++) {
        #pragma unroll
        for (int ni = 0; ni < 4; ni++) {
            int col = bn + wn * 32 + ni * 8 + tig * 2;
            if (col >= N) continue;
            int r0 = bm + wm * 64 + mi * 16 + group;
            if (r0 < M) {
                float2 v = make_float2(acc[mi][ni][0], acc[mi][ni][1]);
                *(float2*)&C[(size_t)r0 * ldc + col] = v;
            }
            int r1 = r0 + 8;
            if (r1 < M) {
                float2 v = make_float2(acc[mi][ni][2], acc[mi][ni][3]);
                *(float2*)&C[(size_t)r1 * ldc + col] = v;
            }
        }
    }
}

// ===========================================================================
// single-term fp16 GEMM: C[M,N] = A[M,K] * B[N,K]^T
// ===========================================================================
#define SMEM_F16 (2 * 2 * TILE_E * 2)   // 40960 B

__global__ __launch_bounds__(256) void gemm_f16_kernel(
    const __half* __restrict__ A, int lda,
    const __half* __restrict__ B, int ldb,
    float* __restrict__ C, int ldc, int M, int N, int K)
{
    extern __shared__ __half smh[];
    const int tid  = threadIdx.x;
    const int lane = tid & 31;
    const int wid  = tid >> 5;
    const int wm   = wid & 1;
    const int wn   = wid >> 1;
    const int bm   = blockIdx.y * BM;
    const int bn   = blockIdx.x * BN;

    __half* sA[2]; __half* sB[2];
    #pragma unroll
    for (int st = 0; st < 2; st++) {
        __half* base = smh + st * 2 * TILE_E;
        sA[st] = base;
        sB[st] = base + TILE_E;
    }

    float acc[4][4][4];
    #pragma unroll
    for (int i = 0; i < 4; i++)
        #pragma unroll
        for (int j = 0; j < 4; j++)
            #pragma unroll
            for (int k = 0; k < 4; k++) acc[i][j][k] = 0.f;

    const int KT = (K + BKT - 1) / BKT;

    auto load_stage = [&](int st, int k0) {
        #pragma unroll
        for (int j = 0; j < 2; j++) {
            int chunk = tid + j * 256;
            int row = chunk >> 2;
            int cc  = chunk & 3;
            int gk  = k0 + cc * 8;
            {
                int gr = bm + row;
                bool p = (gr < M) && (gk < K);
                size_t off = (size_t)(p ? gr : 0) * lda + (p ? gk : 0);
                cpasync16(s2u(sA[st] + row * SROW + cc * 8), A + off, p);
            }
            {
                int gr = bn + row;
                bool p = (gr < N) && (gk < K);
                size_t off = (size_t)(p ? gr : 0) * ldb + (p ? gk : 0);
                cpasync16(s2u(sB[st] + row * SROW + cc * 8), B + off, p);
            }
        }
    };

    load_stage(0, 0);
    asm volatile("cp.async.commit_group;\n");

    for (int kt = 0; kt < KT; kt++) {
        if (kt + 1 < KT) {
            load_stage((kt + 1) & 1, (kt + 1) * BKT);
            asm volatile("cp.async.commit_group;\n");
            asm volatile("cp.async.wait_group 1;\n");
        } else {
            asm volatile("cp.async.wait_group 0;\n");
        }
        __syncthreads();

        int st = kt & 1;
        #pragma unroll
        for (int kk = 0; kk < BKT; kk += 16) {
            uint32_t af[4][4];
            int arow = wm * 64 + (lane & 15);
            int acol = kk + (lane >> 4) * 8;
            #pragma unroll
            for (int mi = 0; mi < 4; mi++)
                ldmatrix_x4(af[mi], s2u(sA[st] + (arow + mi * 16) * SROW + acol));
            int brow = wn * 32 + (lane & 7);
            int bcol = kk + ((lane >> 3) & 1) * 8;
            uint32_t bb[4][2];
            #pragma unroll
            for (int ni = 0; ni < 4; ni++)
                ldmatrix_x2(bb[ni], s2u(sB[st] + (brow + ni * 8) * SROW + bcol));
            #pragma unroll
            for (int mi = 0; mi < 4; mi++)
                #pragma unroll
                for (int ni = 0; ni < 4; ni++)
                    mma16816_f16(acc[mi][ni], af[mi], bb[ni]);
        }
        __syncthreads();
    }

    const int group = lane >> 2;
    const int tig   = lane & 3;
    #pragma unroll
    for (int mi = 0; mi < 4; mi++) {
        #pragma unroll
        for (int ni = 0; ni < 4; ni++) {
            int col = bn + wn * 32 + ni * 8 + tig * 2;
            if (col >= N) continue;
            int r0 = bm + wm * 64 + mi * 16 + group;
            if (r0 < M) {
                float2 v = make_float2(acc[mi][ni][0], acc[mi][ni][1]);
                *(float2*)&C[(size_t)r0 * ldc + col] = v;
            }
            int r1 = r0 + 8;
            if (r1 < M) {
                float2 v = make_float2(acc[mi][ni][2], acc[mi][ni][3]);
                *(float2*)&C[(size_t)r1 * ldc + col] = v;
            }
        }
    }
}

// ---------------------------------------------------------------------------
// CSR build
// ---------------------------------------------------------------------------
__global__ void zero_cnt_kernel(int* cnt, int N)
{
    int i = blockIdx.x * blockDim.x + threadIdx.x;
    if (i < N) cnt[i] = 0;
}

__global__ void count_kernel(const int* __restrict__ dst, int* cnt, int E)
{
    int i = blockIdx.x * blockDim.x + threadIdx.x;
    if (i < E) atomicAdd(&cnt[dst[i]], 1);
}

__global__ void scan_kernel(const int* __restrict__ cnt,
                            int* __restrict__ roff, int* __restrict__ cur, int N)
{
    __shared__ int ssum[1024];
    int t = threadIdx.x;
    int per = (N + 1023) / 1024;
    int b = t * per;
    int loc = 0;
    for (int i = 0; i < per; i++)
        if (b + i < N) loc += cnt[b + i];
    ssum[t] = loc;
    __syncthreads();
    for (int o = 1; o < 1024; o <<= 1) {
        int v = (t >= o) ? ssum[t - o] : 0;
        __syncthreads();
        ssum[t] += v;
        __syncthreads();
    }
    int run = (t == 0) ? 0 : ssum[t - 1];
    for (int i = 0; i < per; i++) {
        if (b + i < N) {
            roff[b + i] = run;
            cur[b + i]  = run;
            run += cnt[b + i];
        }
    }
    if (t == 1023) roff[N] = ssum[1023];
}

__global__ void fill_kernel(const int* __restrict__ src,
                            const int* __restrict__ dst,
                            int* __restrict__ cur, int* __restrict__ rsrc, int E)
{
    int i = blockIdx.x * blockDim.x + threadIdx.x;
    if (i >= E) return;
    int pos = atomicAdd(&cur[dst[i]], 1);
    rsrc[pos] = src[i];
}

// ---------------------------------------------------------------------------
// Attention
// ---------------------------------------------------------------------------
__global__ void dots_kernel(const float* __restrict__ H, int ld, int D,
                            const float* __restrict__ asrc,
                            const float* __restrict__ adst,
                            float* __restrict__ es, float* __restrict__ ed, int N)
{
    int warp = (blockIdx.x * blockDim.x + threadIdx.x) >> 5;
    int lane = threadIdx.x & 31;
    if (warp >= N) return;
    const float* h = H + (size_t)warp * ld;
    float s1 = 0.f, s2 = 0.f;
    for (int d = lane; d < D; d += 32) {
        float v = h[d];
        s1 += v * asrc[d];
        s2 += v * adst[d];
    }
    #pragma unroll
    for (int o = 16; o; o >>= 1) {
        s1 += __shfl_xor_sync(0xffffffffu, s1, o);
        s2 += __shfl_xor_sync(0xffffffffu, s2, o);
    }
    if (lane == 0) { es[warp] = s1; ed[warp] = s2; }
}

// Fused per-node softmax + aggregation + ELU + output convert.
// Perm path: logits gathered via p (es[p[i]] identity) — no separate dots.
// OMODE: 0 = bf16 hi/lo split pair, 1 = single fp16.
#define ACHUNK 64
template <int NCH, int OMODE>
__global__ __launch_bounds__(256) void csr_attn_kernel(
    const float* __restrict__ H, int ldh,
    const int* __restrict__ p,
    const float* __restrict__ es, const float* __restrict__ ed,
    const int* __restrict__ roff, const int* __restrict__ rsrc,
    bf16* __restrict__ outh, bf16* __restrict__ outl,
    int ldo, int coloff)
{
    const int node = blockIdx.x;
    const int tid  = threadIdx.x;
    const int lane = tid & 31;
    const int wid  = tid >> 5;
    const int beg = roff[node];
    const int deg = roff[node + 1] - beg;

    __shared__ float s_w[ACHUNK];
    __shared__ int   s_src[ACHUNK];
    __shared__ float s_ms[2];

    const float edv = ed[p ? p[node] : node];

    if (wid == 0) {
        float m = -INFINITY;
        for (int j = lane; j < deg; j += 32) {
            int sidx = rsrc[beg + j];
            float e = es[p ? p[sidx] : sidx] + edv;
            e = (e >= 0.f) ? e : 0.2f * e;
            m = fmaxf(m, e);
        }
        #pragma unroll
        for (int o = 16; o; o >>= 1) m = fmaxf(m, __shfl_xor_sync(0xffffffffu, m, o));
        float ssum = 0.f;
        for (int j = lane; j < deg; j += 32) {
            int sidx = rsrc[beg + j];
            float e = es[p ? p[sidx] : sidx] + edv;
            e = (e >= 0.f) ? e : 0.2f * e;
            ssum += __expf(e - m);
        }
        #pragma unroll
        for (int o = 16; o; o >>= 1) ssum += __shfl_xor_sync(0xffffffffu, ssum, o);
        if (lane == 0) { s_ms[0] = m; s_ms[1] = ssum; }
    }
    __syncthreads();
    const float m    = s_ms[0];
    const float invs = 1.f / (s_ms[1] + 1e-16f);

    float acc0 = 0.f, acc1 = 0.f;
    for (int c0 = 0; c0 < deg; c0 += ACHUNK) {
        int cl = min(ACHUNK, deg - c0);
        if (tid < cl) {
            int sidx = rsrc[beg + c0 + tid];
            int ps = p ? p[sidx] : sidx;
            float e = es[ps] + edv;
            e = (e >= 0.f) ? e : 0.2f * e;
            s_w[tid]   = __expf(e - m) * invs;
            s_src[tid] = ps;
        }
        __syncthreads();
        for (int j = 0; j < cl; j++) {
            const float* hrow = H + (size_t)s_src[j] * ldh;
            float w = s_w[j];
            acc0 += w * hrow[tid];
            if (NCH == 2) acc1 += w * hrow[tid + 256];
        }
        __syncthreads();
    }

    acc0 = (acc0 > 0.f) ? acc0 : expm1f(acc0);
    if (NCH == 2) acc1 = (acc1 > 0.f) ? acc1 : expm1f(acc1);

    size_t base = (size_t)node * ldo + coloff;
    if (OMODE == 0) {
        bf16 h0 = __float2bfloat16(acc0);
        outh[base + tid] = h0;
        outl[base + tid] = __float2bfloat16(acc0 - __bfloat162float(h0));
        if (NCH == 2) {
            bf16 h1 = __float2bfloat16(acc1);
            outh[base + tid + 256] = h1;
            outl[base + tid + 256] = __float2bfloat16(acc1 - __bfloat162float(h1));
        }
    } else {
        __half* oh = (__half*)outh;
        oh[base + tid] = __float2half(acc0);
        if (NCH == 2) oh[base + tid + 256] = __float2half(acc1);
    }
}

__global__ void summary_kernel(const float* __restrict__ h2, int N, int C,
                               float* __restrict__ out)
{
    int c = blockIdx.x;
    float acc = 0.f;
    for (int r = threadIdx.x; r < N; r += blockDim.x)
        acc += h2[(size_t)r * C + c];
    __shared__ float sh[256];
    sh[threadIdx.x] = acc;
    __syncthreads();
    for (int o = 128; o; o >>= 1) {
        if (threadIdx.x < o) sh[threadIdx.x] += sh[threadIdx.x + o];
        __syncthreads();
    }
    if (threadIdx.x == 0)
        out[c] = 1.f / (1.f + expf(-sh[0] / (float)N));
}

// ---------------------------------------------------------------------------
// Host side
// ---------------------------------------------------------------------------
static void gemm_mma(const bf16* Ah, const bf16* Al, int lda,
                     const bf16* Bh, const bf16* Bl, int ldb,
                     float* C, int ldc, int M, int N, int K)
{
    dim3 grid((N + BN - 1) / BN, (M + BM - 1) / BM);
    gemm_mma_kernel<<<grid, 256, SMEM_BYTES>>>(Ah, Al, lda, Bh, Bl, ldb,
                                               C, ldc, M, N, K);
}

static void gemm_f16(const __half* A, int lda, const __half* B, int ldb,
                     float* C, int ldc, int M, int N, int K)
{
    dim3 grid((N + BN - 1) / BN, (M + BM - 1) / BM);
    gemm_f16_kernel<<<grid, 256, SMEM_F16>>>(A, lda, B, ldb, C, ldc, M, N, K);
}

static void split(const float* x, bf16* hi, bf16* lo, size_t n)
{
    split_kernel<<<(unsigned)((n + 255) / 256), 256>>>(x, hi, lo, n);
}

extern "C" void kernel_launch(void* const* d_in, const int* in_sizes, int n_in,
                              void* d_out, int out_size)
{
    const float* features = (const float*)d_in[0];
    const float* imf      = (const float*)d_in[1];
    const float* W1x      = (const float*)d_in[2];
    const float* a1x_src  = (const float*)d_in[3];
    const float* a1x_dst  = (const float*)d_in[4];
    const float* W1r      = (const float*)d_in[5];
    const float* a1r_src  = (const float*)d_in[6];
    const float* a1r_dst  = (const float*)d_in[7];
    const float* W2       = (const float*)d_in[8];
    const float* a3_src   = (const float*)d_in[9];
    const float* a3_dst   = (const float*)d_in[10];
    const int*   edge     = (const int*)d_in[11];
    const int*   perm     = (const int*)d_in[12];

    const int NH  = in_sizes[3];              // 256
    const int INX = in_sizes[2] / NH;         // 3000
    const int INR = in_sizes[5] / NH;         // 2048
    const int OUT = in_sizes[8] / (2 * NH);   // 64
    const int N   = in_sizes[0] / INX;        // 30000
    const int E   = in_sizes[11] / 2;         // 480000
    const int D2  = 2 * NH;                   // 512

    const int* src = edge;
    const int* dst = edge + E;

    cudaFuncSetAttribute(gemm_mma_kernel,
                         cudaFuncAttributeMaxDynamicSharedMemorySize, SMEM_BYTES);
    cudaFuncSetAttribute(gemm_f16_kernel,
                         cudaFuncAttributeMaxDynamicSharedMemorySize, SMEM_F16);

    bf16 *Ah, *Al;
    __half *W1xT_f16, *W1rT_f16, *W1x_f16, *W1r_f16;
    bf16 *W2T_h, *W2T_l, *W2_h, *W2_l;
    float *Hx, *Hr, *Abuf, *es, *ed, *esx, *edx, *esr, *edr;
    int *roff, *cnt, *cur, *rsrc;
    cudaGetSymbolAddress((void**)&Ah,   g_Ah);
    cudaGetSymbolAddress((void**)&Al,   g_Al);
    cudaGetSymbolAddress((void**)&Hx,   g_Hx);
    cudaGetSymbolAddress((void**)&Hr,   g_Hr);
    cudaGetSymbolAddress((void**)&Abuf, g_A);
    cudaGetSymbolAddress((void**)&es,   g_es);
    cudaGetSymbolAddress((void**)&ed,   g_ed);
    cudaGetSymbolAddress((void**)&esx,  g_esx);
    cudaGetSymbolAddress((void**)&edx,  g_edx);
    cudaGetSymbolAddress((void**)&esr,  g_esr);
    cudaGetSymbolAddress((void**)&edr,  g_edr);
    cudaGetSymbolAddress((void**)&roff, g_roff);
    cudaGetSymbolAddress((void**)&cnt,  g_cnt);
    cudaGetSymbolAddress((void**)&cur,  g_cur);
    cudaGetSymbolAddress((void**)&rsrc, g_rsrc);
    cudaGetSymbolAddress((void**)&W1xT_f16, g_W1xT_f16);
    cudaGetSymbolAddress((void**)&W1rT_f16, g_W1rT_f16);
    cudaGetSymbolAddress((void**)&W1x_f16,  g_W1x_f16);
    cudaGetSymbolAddress((void**)&W1r_f16,  g_W1r_f16);
    cudaGetSymbolAddress((void**)&W2T_h,  g_W2T_h);
    cudaGetSymbolAddress((void**)&W2T_l,  g_W2T_l);
    cudaGetSymbolAddress((void**)&W2_h,   g_W2_h);
    cudaGetSymbolAddress((void**)&W2_l,   g_W2_l);

    float* out = (float*)d_out;
    float* o_h2   = out;
    float* o_h4x  = o_h2   + (size_t)N * OUT;
    float* o_h4r  = o_h4x  + (size_t)N * INX;
    float* o_rh2  = o_h4r  + (size_t)N * INR;
    float* o_rh4x = o_rh2  + (size_t)N * OUT;
    float* o_rh4r = o_rh4x + (size_t)N * INX;
    float* o_sum  = o_rh4r + (size_t)N * INR;

    // ---- CSR build ----
    zero_cnt_kernel<<<(N + 255) / 256, 256>>>(cnt, N);
    count_kernel<<<(E + 255) / 256, 256>>>(dst, cnt, E);
    scan_kernel<<<1, 1024>>>(cnt, roff, cur, N);
    fill_kernel<<<(E + 255) / 256, 256>>>(src, dst, cur, rsrc, E);

    // ---- weight preps ----
    tcvt_f16_kernel<<<(INX * NH + 255) / 256, 256>>>(W1x, INX, NH, W1xT_f16);
    tcvt_f16_kernel<<<(INR * NH + 255) / 256, 256>>>(W1r, INR, NH, W1rT_f16);
    tsplit_kernel<<<(D2 * OUT + 255) / 256, 256>>>(W2, D2, OUT, W2T_h, W2T_l);
    split(W2, W2_h, W2_l, (size_t)D2 * OUT);
    cvt_f16_kernel<<<(INX * NH + 255) / 256, 256>>>(W1x, W1x_f16, (size_t)INX * NH);
    cvt_f16_kernel<<<(INR * NH + 255) / 256, 256>>>(W1r, W1r_f16, (size_t)INR * NH);

    // ---- shared pre-attention features: fp16 single-term GEMM ----
    __half* Af16 = (__half*)Ah;
    cvt_f16_kernel<<<(unsigned)(((size_t)N * INX + 255) / 256), 256>>>(
        features, Af16, (size_t)N * INX);
    gemm_f16(Af16, INX, W1xT_f16, INX, Hx, NH, N, NH, INX);
    cvt_f16_kernel<<<(unsigned)(((size_t)N * INR + 255) / 256), 256>>>(
        imf, Af16, (size_t)N * INR);
    gemm_f16(Af16, INR, W1rT_f16, INR, Hr, NH, N, NH, INR);

    // ---- encode dots once (perm path uses gather identity) ----
    dots_kernel<<<(N + 7) / 8, 256>>>(Hx, NH, NH, a1x_src, a1x_dst, esx, edx, N);
    dots_kernel<<<(N + 7) / 8, 256>>>(Hr, NH, NH, a1r_src, a1r_dst, esr, edr, N);

    for (int path = 0; path < 2; path++) {
        const int* p = path ? perm : nullptr;
        float* oh2  = path ? o_rh2  : o_h2;
        float* oh4x = path ? o_rh4x : o_h4x;
        float* oh4r = path ? o_rh4r : o_h4r;

        // --- encode: GAT layers (bf16 split out) -> @W2 (3-term) ---
        csr_attn_kernel<1, 0><<<N, 256>>>(Hx, NH, p, esx, edx, roff, rsrc,
                                          Ah, Al, D2, 0);
        csr_attn_kernel<1, 0><<<N, 256>>>(Hr, NH, p, esr, edr, roff, rsrc,
                                          Ah, Al, D2, NH);
        gemm_mma(Ah, Al, D2, W2T_h, W2T_l, D2, oh2, OUT, N, OUT, D2);

        // --- decode: hd = h2 @ W2^T (3-term), GAT (fp16 out), project (fp16) ---
        split(oh2, Ah, Al, (size_t)N * OUT);
        gemm_mma(Ah, Al, OUT, W2_h, W2_l, OUT, Abuf, D2, N, D2, OUT);

        dots_kernel<<<(N + 7) / 8, 256>>>(Abuf, D2, D2, a3_src, a3_dst, es, ed, N);
        csr_attn_kernel<2, 1><<<N, 256>>>(Abuf, D2, nullptr, es, ed, roff, rsrc,
                                          Ah, nullptr, D2, 0);

        const __half* H3 = (const __half*)Ah;
        gemm_f16(H3,      D2, W1x_f16, NH, oh4x, INX, N, INX, NH);
        gemm_f16(H3 + NH, D2, W1r_f16, NH, oh4r, INR, N, INR, NH);
    }

    summary_kernel<<<OUT, 256>>>(o_h2, N, OUT, o_sum);
}